// round 3
// baseline (speedup 1.0000x reference)
#include <cuda_runtime.h>
#include <math.h>

// ---------------- scratch (device globals; no allocation allowed) ----------
#define NTOK 4096            // B*S = 2*2048
#define EMB  1024
#define FFD  4096

__device__ float g_ln1[NTOK * EMB];
__device__ float g_q  [NTOK * EMB];
__device__ float g_k  [NTOK * EMB];
__device__ float g_v  [NTOK * EMB];
__device__ float g_z  [NTOK * EMB];
__device__ float g_h  [NTOK * EMB];
__device__ float g_ln2[NTOK * EMB];
__device__ float g_ff [NTOK * FFD];

// ---------------- LayerNorm: one block per row of 1024 ---------------------
__global__ void __launch_bounds__(256) layernorm_kernel(
    const float* __restrict__ x, const float* __restrict__ g,
    const float* __restrict__ b, float* __restrict__ out)
{
    int row = blockIdx.x;
    int tid = threadIdx.x;
    const float4* xr = (const float4*)(x + (size_t)row * EMB);
    float4 v = xr[tid];
    float s  = v.x + v.y + v.z + v.w;
    float ss = v.x*v.x + v.y*v.y + v.z*v.z + v.w*v.w;
    #pragma unroll
    for (int off = 16; off > 0; off >>= 1) {
        s  += __shfl_xor_sync(0xffffffffu, s,  off);
        ss += __shfl_xor_sync(0xffffffffu, ss, off);
    }
    __shared__ float sbuf[8], ssbuf[8], red[2];
    int warp = tid >> 5, lane = tid & 31;
    if (lane == 0) { sbuf[warp] = s; ssbuf[warp] = ss; }
    __syncthreads();
    if (tid < 32) {
        float a = (tid < 8) ? sbuf[tid]  : 0.f;
        float c = (tid < 8) ? ssbuf[tid] : 0.f;
        #pragma unroll
        for (int off = 4; off > 0; off >>= 1) {
            a += __shfl_xor_sync(0xffffffffu, a, off);
            c += __shfl_xor_sync(0xffffffffu, c, off);
        }
        if (tid == 0) { red[0] = a; red[1] = c; }
    }
    __syncthreads();
    float mu   = red[0] * (1.0f / EMB);
    float var  = red[1] * (1.0f / EMB) - mu * mu;
    float rstd = rsqrtf(var + 1e-5f);
    float4 gg = ((const float4*)g)[tid];
    float4 bb = ((const float4*)b)[tid];
    float4 o;
    o.x = (v.x - mu) * rstd * gg.x + bb.x;
    o.y = (v.y - mu) * rstd * gg.y + bb.y;
    o.z = (v.z - mu) * rstd * gg.z + bb.z;
    o.w = (v.w - mu) * rstd * gg.w + bb.w;
    ((float4*)(out + (size_t)row * EMB))[tid] = o;
}

// ---------------- SGEMM: C[M,N] = A[M,K] @ W[K,N] (+bias)(gelu)(+res) ------
// 128x128 tile, BK=8, 256 threads, 8x8 micro-tile per thread.
template<bool BIAS, bool GELU, bool RES>
__global__ void __launch_bounds__(256) sgemm_kernel(
    const float* __restrict__ A, const float* __restrict__ W,
    const float* __restrict__ bias, const float* __restrict__ res,
    float* __restrict__ C, int M, int N, int K)
{
    __shared__ float As[8][128];
    __shared__ float Bs[8][128];
    int tid = threadIdx.x;
    int m0 = blockIdx.y * 128, n0 = blockIdx.x * 128;

    int arow = tid >> 1;            // 0..127
    int acol = (tid & 1) << 2;      // 0 or 4
    int brow = tid >> 5;            // 0..7
    int bcol = (tid & 31) << 2;     // 0..124

    const float* Ag = A + (size_t)(m0 + arow) * K + acol;
    const float* Bg = W + (size_t)brow * N + n0 + bcol;

    float acc[8][8];
    #pragma unroll
    for (int i = 0; i < 8; i++)
        #pragma unroll
        for (int j = 0; j < 8; j++) acc[i][j] = 0.f;

    int ty = tid >> 4, tx = tid & 15;

    for (int k0 = 0; k0 < K; k0 += 8) {
        float4 a4 = *(const float4*)(Ag + k0);
        float4 b4 = *(const float4*)(Bg + (size_t)k0 * N);
        As[acol + 0][arow] = a4.x;
        As[acol + 1][arow] = a4.y;
        As[acol + 2][arow] = a4.z;
        As[acol + 3][arow] = a4.w;
        *(float4*)&Bs[brow][bcol] = b4;
        __syncthreads();
        #pragma unroll
        for (int k = 0; k < 8; k++) {
            float a[8], bb[8];
            *(float4*)(a)     = *(const float4*)&As[k][ty * 8];
            *(float4*)(a + 4) = *(const float4*)&As[k][ty * 8 + 4];
            *(float4*)(bb)     = *(const float4*)&Bs[k][tx * 8];
            *(float4*)(bb + 4) = *(const float4*)&Bs[k][tx * 8 + 4];
            #pragma unroll
            for (int i = 0; i < 8; i++)
                #pragma unroll
                for (int j = 0; j < 8; j++)
                    acc[i][j] += a[i] * bb[j];
        }
        __syncthreads();
    }

    #pragma unroll
    for (int i = 0; i < 8; i++) {
        int row = m0 + ty * 8 + i;
        #pragma unroll
        for (int j4 = 0; j4 < 8; j4 += 4) {
            int col = n0 + tx * 8 + j4;
            float4 c4;
            c4.x = acc[i][j4 + 0]; c4.y = acc[i][j4 + 1];
            c4.z = acc[i][j4 + 2]; c4.w = acc[i][j4 + 3];
            if (BIAS) {
                float4 bq = *(const float4*)(bias + col);
                c4.x += bq.x; c4.y += bq.y; c4.z += bq.z; c4.w += bq.w;
            }
            if (GELU) {
                c4.x = 0.5f * c4.x * (1.0f + erff(c4.x * 0.70710678118654752f));
                c4.y = 0.5f * c4.y * (1.0f + erff(c4.y * 0.70710678118654752f));
                c4.z = 0.5f * c4.z * (1.0f + erff(c4.z * 0.70710678118654752f));
                c4.w = 0.5f * c4.w * (1.0f + erff(c4.w * 0.70710678118654752f));
            }
            if (RES) {
                float4 r4 = *(const float4*)(res + (size_t)row * N + col);
                c4.x += r4.x; c4.y += r4.y; c4.z += r4.z; c4.w += r4.w;
            }
            *(float4*)(C + (size_t)row * N + col) = c4;
        }
    }
}

// ---------------- Flash attention (fp32, causal, scale 1/sqrt(1024)) -------
// Q,K,V,O layout: [B, S, H*64]. Block: 64 queries x one (b,h). 256 threads,
// 4x4 micro-tile over [64 rows x 64 cols].
#define FA_PAD 68
__global__ void __launch_bounds__(256) flash_kernel(
    const float* __restrict__ Q, const float* __restrict__ Kg,
    const float* __restrict__ Vg, float* __restrict__ O)
{
    extern __shared__ float sm[];
    float* Qs  = sm;                 // [64][68]  (r, d)
    float* Kts = Qs  + 64 * FA_PAD;  // [64][68]  (d, c)  transposed K
    float* Vs  = Kts + 64 * FA_PAD;  // [64][68]  (c, d)
    float* Ps  = Vs  + 64 * FA_PAD;  // [64][68]  (r, c)

    int tid = threadIdx.x;
    int ty = tid >> 4, tx = tid & 15;
    int bh = blockIdx.y;
    int b = bh >> 4, h = bh & 15;
    int qb = blockIdx.x;
    int qbase = qb * 64;
    const size_t base = ((size_t)b * 2048) * EMB + h * 64;

    // load Q tile
    for (int it = tid; it < 64 * 16; it += 256) {
        int r = it >> 4, d4 = (it & 15) << 2;
        float4 v = *(const float4*)(Q + base + (size_t)(qbase + r) * EMB + d4);
        *(float4*)&Qs[r * FA_PAD + d4] = v;
    }

    float m_i[4], l_i[4], acc[4][4];
    #pragma unroll
    for (int i = 0; i < 4; i++) {
        m_i[i] = -1e30f; l_i[i] = 0.f;
        #pragma unroll
        for (int j = 0; j < 4; j++) acc[i][j] = 0.f;
    }
    __syncthreads();

    const float scale = 0.03125f;  // 1/sqrt(1024)

    for (int t = 0; t <= qb; t++) {
        int kbase = t * 64;
        // load K (transposed) and V tiles
        for (int it = tid; it < 64 * 16; it += 256) {
            int c = it >> 4, d4 = (it & 15) << 2;
            float4 kv = *(const float4*)(Kg + base + (size_t)(kbase + c) * EMB + d4);
            Kts[(d4 + 0) * FA_PAD + c] = kv.x;
            Kts[(d4 + 1) * FA_PAD + c] = kv.y;
            Kts[(d4 + 2) * FA_PAD + c] = kv.z;
            Kts[(d4 + 3) * FA_PAD + c] = kv.w;
            float4 vv = *(const float4*)(Vg + base + (size_t)(kbase + c) * EMB + d4);
            *(float4*)&Vs[c * FA_PAD + d4] = vv;
        }
        __syncthreads();

        // S = scale * Q K^T  (thread: rows 4ty..+3, cols 4tx..+3)
        float s[4][4];
        #pragma unroll
        for (int i = 0; i < 4; i++)
            #pragma unroll
            for (int j = 0; j < 4; j++) s[i][j] = 0.f;

        #pragma unroll 8
        for (int k = 0; k < 64; k++) {
            float a0 = Qs[(4 * ty + 0) * FA_PAD + k];
            float a1 = Qs[(4 * ty + 1) * FA_PAD + k];
            float a2 = Qs[(4 * ty + 2) * FA_PAD + k];
            float a3 = Qs[(4 * ty + 3) * FA_PAD + k];
            float4 kb4 = *(const float4*)&Kts[k * FA_PAD + 4 * tx];
            s[0][0] += a0 * kb4.x; s[0][1] += a0 * kb4.y; s[0][2] += a0 * kb4.z; s[0][3] += a0 * kb4.w;
            s[1][0] += a1 * kb4.x; s[1][1] += a1 * kb4.y; s[1][2] += a1 * kb4.z; s[1][3] += a1 * kb4.w;
            s[2][0] += a2 * kb4.x; s[2][1] += a2 * kb4.y; s[2][2] += a2 * kb4.z; s[2][3] += a2 * kb4.w;
            s[3][0] += a3 * kb4.x; s[3][1] += a3 * kb4.y; s[3][2] += a3 * kb4.z; s[3][3] += a3 * kb4.w;
        }

        bool diag = (t == qb);
        #pragma unroll
        for (int i = 0; i < 4; i++) {
            int r = 4 * ty + i;
            #pragma unroll
            for (int j = 0; j < 4; j++) {
                s[i][j] *= scale;
                if (diag && (kbase + 4 * tx + j) > (qbase + r)) s[i][j] = -1e30f;
            }
        }

        // online softmax update
        #pragma unroll
        for (int i = 0; i < 4; i++) {
            float tmax = fmaxf(fmaxf(s[i][0], s[i][1]), fmaxf(s[i][2], s[i][3]));
            #pragma unroll
            for (int off = 8; off > 0; off >>= 1)
                tmax = fmaxf(tmax, __shfl_xor_sync(0xffffffffu, tmax, off));
            float mnew = fmaxf(m_i[i], tmax);
            float alpha = __expf(m_i[i] - mnew);
            float p0 = __expf(s[i][0] - mnew);
            float p1 = __expf(s[i][1] - mnew);
            float p2 = __expf(s[i][2] - mnew);
            float p3 = __expf(s[i][3] - mnew);
            float rs = p0 + p1 + p2 + p3;
            #pragma unroll
            for (int off = 8; off > 0; off >>= 1)
                rs += __shfl_xor_sync(0xffffffffu, rs, off);
            l_i[i] = l_i[i] * alpha + rs;
            m_i[i] = mnew;
            #pragma unroll
            for (int j = 0; j < 4; j++) acc[i][j] *= alpha;
            float4 p4; p4.x = p0; p4.y = p1; p4.z = p2; p4.w = p3;
            *(float4*)&Ps[(4 * ty + i) * FA_PAD + 4 * tx] = p4;
        }
        __syncthreads();

        // acc += P @ V
        #pragma unroll 8
        for (int k = 0; k < 64; k++) {
            float a0 = Ps[(4 * ty + 0) * FA_PAD + k];
            float a1 = Ps[(4 * ty + 1) * FA_PAD + k];
            float a2 = Ps[(4 * ty + 2) * FA_PAD + k];
            float a3 = Ps[(4 * ty + 3) * FA_PAD + k];
            float4 v4 = *(const float4*)&Vs[k * FA_PAD + 4 * tx];
            acc[0][0] += a0 * v4.x; acc[0][1] += a0 * v4.y; acc[0][2] += a0 * v4.z; acc[0][3] += a0 * v4.w;
            acc[1][0] += a1 * v4.x; acc[1][1] += a1 * v4.y; acc[1][2] += a1 * v4.z; acc[1][3] += a1 * v4.w;
            acc[2][0] += a2 * v4.x; acc[2][1] += a2 * v4.y; acc[2][2] += a2 * v4.z; acc[2][3] += a2 * v4.w;
            acc[3][0] += a3 * v4.x; acc[3][1] += a3 * v4.y; acc[3][2] += a3 * v4.z; acc[3][3] += a3 * v4.w;
        }
        __syncthreads();
    }

    // write out O = acc / l
    #pragma unroll
    for (int i = 0; i < 4; i++) {
        float inv = 1.0f / l_i[i];
        float4 o4;
        o4.x = acc[i][0] * inv; o4.y = acc[i][1] * inv;
        o4.z = acc[i][2] * inv; o4.w = acc[i][3] * inv;
        *(float4*)(O + base + (size_t)(qbase + 4 * ty + i) * EMB + 4 * tx) = o4;
    }
}

// ---------------- launch ----------------------------------------------------
extern "C" void kernel_launch(void* const* d_in, const int* in_sizes, int n_in,
                              void* d_out, int out_size)
{
    const float* x   = (const float*)d_in[0];
    const float* Wq  = (const float*)d_in[1];
    const float* bq  = (const float*)d_in[2];
    const float* Wk  = (const float*)d_in[3];
    const float* bk  = (const float*)d_in[4];
    const float* Wv  = (const float*)d_in[5];
    const float* bv  = (const float*)d_in[6];
    const float* Wo  = (const float*)d_in[7];
    const float* W1  = (const float*)d_in[8];
    const float* b1  = (const float*)d_in[9];
    const float* W2  = (const float*)d_in[10];
    const float* b2  = (const float*)d_in[11];
    const float* g1  = (const float*)d_in[12];
    const float* be1 = (const float*)d_in[13];
    const float* g2  = (const float*)d_in[14];
    const float* be2 = (const float*)d_in[15];
    float* out = (float*)d_out;

    float *ln1, *qb, *kb, *vb, *zb, *hb, *ln2b, *ffb;
    cudaGetSymbolAddress((void**)&ln1,  g_ln1);
    cudaGetSymbolAddress((void**)&qb,   g_q);
    cudaGetSymbolAddress((void**)&kb,   g_k);
    cudaGetSymbolAddress((void**)&vb,   g_v);
    cudaGetSymbolAddress((void**)&zb,   g_z);
    cudaGetSymbolAddress((void**)&hb,   g_h);
    cudaGetSymbolAddress((void**)&ln2b, g_ln2);
    cudaGetSymbolAddress((void**)&ffb,  g_ff);

    // 1) ln1 = LN(x)
    layernorm_kernel<<<NTOK, 256>>>(x, g1, be1, ln1);

    // 2) Q, K, V projections (bias fused)
    sgemm_kernel<true, false, false><<<dim3(EMB / 128, NTOK / 128), 256>>>(
        ln1, Wq, bq, nullptr, qb, NTOK, EMB, EMB);
    sgemm_kernel<true, false, false><<<dim3(EMB / 128, NTOK / 128), 256>>>(
        ln1, Wk, bk, nullptr, kb, NTOK, EMB, EMB);
    sgemm_kernel<true, false, false><<<dim3(EMB / 128, NTOK / 128), 256>>>(
        ln1, Wv, bv, nullptr, vb, NTOK, EMB, EMB);

    // 3) causal flash attention
    cudaFuncSetAttribute(flash_kernel, cudaFuncAttributeMaxDynamicSharedMemorySize,
                         4 * 64 * FA_PAD * sizeof(float));
    flash_kernel<<<dim3(32, 32), 256, 4 * 64 * FA_PAD * sizeof(float)>>>(qb, kb, vb, zb);

    // 4) h = x + z @ Wo
    sgemm_kernel<false, false, true><<<dim3(EMB / 128, NTOK / 128), 256>>>(
        zb, Wo, nullptr, x, hb, NTOK, EMB, EMB);

    // 5) ln2 = LN(h)
    layernorm_kernel<<<NTOK, 256>>>(hb, g2, be2, ln2b);

    // 6) ff = gelu(ln2 @ W1 + b1)
    sgemm_kernel<true, true, false><<<dim3(FFD / 128, NTOK / 128), 256>>>(
        ln2b, W1, b1, nullptr, ffb, NTOK, FFD, EMB);

    // 7) out = h + ff @ W2 + b2
    sgemm_kernel<true, false, true><<<dim3(EMB / 128, NTOK / 128), 256>>>(
        ffb, W2, b2, hb, out, NTOK, EMB, FFD);
}

// round 4
// speedup vs baseline: 1.5639x; 1.5639x over previous
#include <cuda_runtime.h>
#include <math.h>

// ---------------- scratch (device globals; no allocation allowed) ----------
#define NTOK 4096            // B*S = 2*2048
#define EMB  1024
#define FFD  4096

__device__ float g_ln1[NTOK * EMB];
__device__ float g_q  [NTOK * EMB];
__device__ float g_k  [NTOK * EMB];
__device__ float g_v  [NTOK * EMB];
__device__ float g_z  [NTOK * EMB];
__device__ float g_h  [NTOK * EMB];
__device__ float g_ln2[NTOK * EMB];
__device__ float g_ff [NTOK * FFD];
// tf32-rounded weight copies
__device__ float g_wq[EMB * EMB];
__device__ float g_wk[EMB * EMB];
__device__ float g_wv[EMB * EMB];
__device__ float g_wo[EMB * EMB];
__device__ float g_w1[EMB * FFD];
__device__ float g_w2[FFD * EMB];

// ---------------- helpers ---------------------------------------------------
__device__ __forceinline__ float tf32_rna(float f) {
    unsigned u;
    asm("cvt.rna.tf32.f32 %0, %1;" : "=r"(u) : "f"(f));
    return __uint_as_float(u);
}

#define CP_ASYNC16(dst_u32, src_ptr) \
    asm volatile("cp.async.cg.shared.global [%0], [%1], 16;" :: "r"(dst_u32), "l"(src_ptr))
#define CP_COMMIT() asm volatile("cp.async.commit_group;")
#define CP_WAIT1()  asm volatile("cp.async.wait_group 1;")
#define CP_WAIT0()  asm volatile("cp.async.wait_group 0;")

// ---------------- round-copy (weights -> tf32-rounded copies) ---------------
__global__ void __launch_bounds__(256) round_copy_kernel(
    const float* __restrict__ in, float* __restrict__ out, int n4)
{
    int i = blockIdx.x * blockDim.x + threadIdx.x;
    if (i < n4) {
        float4 v = ((const float4*)in)[i];
        v.x = tf32_rna(v.x); v.y = tf32_rna(v.y);
        v.z = tf32_rna(v.z); v.w = tf32_rna(v.w);
        ((float4*)out)[i] = v;
    }
}

// ---------------- LayerNorm (output rounded to tf32: feeds GEMMs only) ------
__global__ void __launch_bounds__(256) layernorm_kernel(
    const float* __restrict__ x, const float* __restrict__ g,
    const float* __restrict__ b, float* __restrict__ out)
{
    int row = blockIdx.x;
    int tid = threadIdx.x;
    const float4* xr = (const float4*)(x + (size_t)row * EMB);
    float4 v = xr[tid];
    float s  = v.x + v.y + v.z + v.w;
    float ss = v.x*v.x + v.y*v.y + v.z*v.z + v.w*v.w;
    #pragma unroll
    for (int off = 16; off > 0; off >>= 1) {
        s  += __shfl_xor_sync(0xffffffffu, s,  off);
        ss += __shfl_xor_sync(0xffffffffu, ss, off);
    }
    __shared__ float sbuf[8], ssbuf[8], red[2];
    int warp = tid >> 5, lane = tid & 31;
    if (lane == 0) { sbuf[warp] = s; ssbuf[warp] = ss; }
    __syncthreads();
    if (tid < 32) {
        float a = (tid < 8) ? sbuf[tid]  : 0.f;
        float c = (tid < 8) ? ssbuf[tid] : 0.f;
        #pragma unroll
        for (int off = 4; off > 0; off >>= 1) {
            a += __shfl_xor_sync(0xffffffffu, a, off);
            c += __shfl_xor_sync(0xffffffffu, c, off);
        }
        if (tid == 0) { red[0] = a; red[1] = c; }
    }
    __syncthreads();
    float mu   = red[0] * (1.0f / EMB);
    float var  = red[1] * (1.0f / EMB) - mu * mu;
    float rstd = rsqrtf(var + 1e-5f);
    float4 gg = ((const float4*)g)[tid];
    float4 bb = ((const float4*)b)[tid];
    float4 o;
    o.x = tf32_rna((v.x - mu) * rstd * gg.x + bb.x);
    o.y = tf32_rna((v.y - mu) * rstd * gg.y + bb.y);
    o.z = tf32_rna((v.z - mu) * rstd * gg.z + bb.z);
    o.w = tf32_rna((v.w - mu) * rstd * gg.w + bb.w);
    ((float4*)(out + (size_t)row * EMB))[tid] = o;
}

// ---------------- TF32 tensor-core GEMM -------------------------------------
// C[M,N] = A[M,K] @ W[K,N] (+bias)(gelu)(+res)(round-out).
// A and W MUST already be tf32-rounded fp32. 128x128x32 tile, 256 threads,
// 8 warps in 4(M)x2(N); warp tile 32x64 -> 2x8 m16n8k8 mmas per k8-step.
// cp.async double-buffered smem; A pitch 36, B pitch 136 (conflict-free frags).
#define APITCH 36
#define BPITCH 136
#define AS_ELEMS (128 * APITCH)
#define BS_ELEMS (32  * BPITCH)
#define GEMM_SMEM ((2 * AS_ELEMS + 2 * BS_ELEMS) * 4)

template<bool BIAS, bool GELU, bool RES, bool ROUND>
__global__ void __launch_bounds__(256, 2) gemm_tf32_kernel(
    const float* __restrict__ A, const float* __restrict__ W,
    const float* __restrict__ bias, const float* __restrict__ res,
    float* __restrict__ C, int M, int N, int K)
{
    extern __shared__ float sm[];
    float* As = sm;                      // [2][128][APITCH]  (row m, col k)
    float* Bs = sm + 2 * AS_ELEMS;       // [2][32][BPITCH]   (row k, col n)

    const int tid  = threadIdx.x;
    const int lane = tid & 31;
    const int warp = tid >> 5;
    const int wm   = warp & 3;           // 0..3
    const int wn   = warp >> 2;          // 0..1
    const int lm   = lane >> 2;          // 0..7
    const int lk   = lane & 3;           // 0..3
    const int m0 = blockIdx.y * 128, n0 = blockIdx.x * 128;

    // global load coordinates (4 float4 each for A and B per thread)
    const int a_row = tid >> 3;           // base, +32 per l? no: idx layout below
    // A: idx = tid + l*256 ; row = idx>>3 (0..127), kc = (idx&7)*4
    // B: idx = tid + l*256 ; kr  = idx>>5 (0..31),  nc = (idx&31)*4
    (void)a_row;

    unsigned as_base = (unsigned)__cvta_generic_to_shared(As);
    unsigned bs_base = (unsigned)__cvta_generic_to_shared(Bs);

    float acc[2][8][4];
    #pragma unroll
    for (int i = 0; i < 2; i++)
        #pragma unroll
        for (int j = 0; j < 8; j++)
            #pragma unroll
            for (int q = 0; q < 4; q++) acc[i][j][q] = 0.f;

    const int T = K / 32;

    // ---- issue stage 0 ----
    {
        #pragma unroll
        for (int l = 0; l < 4; l++) {
            int idx = tid + l * 256;
            int row = idx >> 3, kc = (idx & 7) << 2;
            const float* src = A + (size_t)(m0 + row) * K + kc;
            unsigned dst = as_base + (unsigned)((row * APITCH + kc) * 4);
            CP_ASYNC16(dst, src);
        }
        #pragma unroll
        for (int l = 0; l < 4; l++) {
            int idx = tid + l * 256;
            int kr = idx >> 5, nc = (idx & 31) << 2;
            const float* src = W + (size_t)kr * N + n0 + nc;
            unsigned dst = bs_base + (unsigned)((kr * BPITCH + nc) * 4);
            CP_ASYNC16(dst, src);
        }
        CP_COMMIT();
    }

    for (int it = 0; it < T; it++) {
        // ---- issue stage it+1 ----
        if (it + 1 < T) {
            int st = (it + 1) & 1;
            int k0 = (it + 1) * 32;
            #pragma unroll
            for (int l = 0; l < 4; l++) {
                int idx = tid + l * 256;
                int row = idx >> 3, kc = (idx & 7) << 2;
                const float* src = A + (size_t)(m0 + row) * K + k0 + kc;
                unsigned dst = as_base + (unsigned)((st * AS_ELEMS + row * APITCH + kc) * 4);
                CP_ASYNC16(dst, src);
            }
            #pragma unroll
            for (int l = 0; l < 4; l++) {
                int idx = tid + l * 256;
                int kr = idx >> 5, nc = (idx & 31) << 2;
                const float* src = W + (size_t)(k0 + kr) * N + n0 + nc;
                unsigned dst = bs_base + (unsigned)((st * BS_ELEMS + kr * BPITCH + nc) * 4);
                CP_ASYNC16(dst, src);
            }
            CP_COMMIT();
            CP_WAIT1();
        } else {
            CP_WAIT0();
        }
        __syncthreads();

        const int st = it & 1;
        const float* Asb = As + st * AS_ELEMS;
        const float* Bsb = Bs + st * BS_ELEMS;

        #pragma unroll
        for (int kk = 0; kk < 4; kk++) {
            const int kb = kk * 8;
            unsigned b[8][2], a[2][4];
            #pragma unroll
            for (int jn = 0; jn < 8; jn++) {
                int col = wn * 64 + jn * 8 + lm;
                b[jn][0] = __float_as_uint(Bsb[(kb + lk) * BPITCH + col]);
                b[jn][1] = __float_as_uint(Bsb[(kb + 4 + lk) * BPITCH + col]);
            }
            #pragma unroll
            for (int im = 0; im < 2; im++) {
                int row = wm * 32 + im * 16 + lm;
                a[im][0] = __float_as_uint(Asb[row       * APITCH + kb + lk]);
                a[im][1] = __float_as_uint(Asb[(row + 8) * APITCH + kb + lk]);
                a[im][2] = __float_as_uint(Asb[row       * APITCH + kb + 4 + lk]);
                a[im][3] = __float_as_uint(Asb[(row + 8) * APITCH + kb + 4 + lk]);
            }
            #pragma unroll
            for (int im = 0; im < 2; im++)
                #pragma unroll
                for (int jn = 0; jn < 8; jn++) {
                    asm volatile(
                        "mma.sync.aligned.m16n8k8.row.col.f32.tf32.tf32.f32 "
                        "{%0,%1,%2,%3}, {%4,%5,%6,%7}, {%8,%9}, {%0,%1,%2,%3};"
                        : "+f"(acc[im][jn][0]), "+f"(acc[im][jn][1]),
                          "+f"(acc[im][jn][2]), "+f"(acc[im][jn][3])
                        : "r"(a[im][0]), "r"(a[im][1]), "r"(a[im][2]), "r"(a[im][3]),
                          "r"(b[jn][0]), "r"(b[jn][1]));
                }
        }
        __syncthreads();
    }

    // ---- epilogue ----
    #pragma unroll
    for (int im = 0; im < 2; im++) {
        int r0 = m0 + wm * 32 + im * 16 + lm;   // rows r0 and r0+8
        #pragma unroll
        for (int jn = 0; jn < 8; jn++) {
            int c = n0 + wn * 64 + jn * 8 + lk * 2;
            float v[4] = { acc[im][jn][0], acc[im][jn][1],
                           acc[im][jn][2], acc[im][jn][3] };
            if (BIAS) {
                float2 bq = *(const float2*)(bias + c);
                v[0] += bq.x; v[1] += bq.y; v[2] += bq.x; v[3] += bq.y;
            }
            if (GELU) {
                #pragma unroll
                for (int q = 0; q < 4; q++)
                    v[q] = 0.5f * v[q] * (1.0f + erff(v[q] * 0.70710678118654752f));
            }
            if (RES) {
                float2 rlo = *(const float2*)(res + (size_t)r0 * N + c);
                float2 rhi = *(const float2*)(res + (size_t)(r0 + 8) * N + c);
                v[0] += rlo.x; v[1] += rlo.y; v[2] += rhi.x; v[3] += rhi.y;
            }
            if (ROUND) {
                #pragma unroll
                for (int q = 0; q < 4; q++) v[q] = tf32_rna(v[q]);
            }
            float2 lo; lo.x = v[0]; lo.y = v[1];
            float2 hi; hi.x = v[2]; hi.y = v[3];
            *(float2*)(C + (size_t)r0 * N + c)       = lo;
            *(float2*)(C + (size_t)(r0 + 8) * N + c) = hi;
        }
    }
}

// ---------------- Flash attention (fp32, causal, scale 1/sqrt(1024)) -------
// Output rounded to tf32 (feeds the Wo GEMM).
#define FA_PAD 68
__global__ void __launch_bounds__(256) flash_kernel(
    const float* __restrict__ Q, const float* __restrict__ Kg,
    const float* __restrict__ Vg, float* __restrict__ O)
{
    extern __shared__ float smfa[];
    float* Qs  = smfa;               // [64][68]  (r, d)
    float* Kts = Qs  + 64 * FA_PAD;  // [64][68]  (d, c)  transposed K
    float* Vs  = Kts + 64 * FA_PAD;  // [64][68]  (c, d)
    float* Ps  = Vs  + 64 * FA_PAD;  // [64][68]  (r, c)

    int tid = threadIdx.x;
    int ty = tid >> 4, tx = tid & 15;
    int bh = blockIdx.y;
    int b = bh >> 4, h = bh & 15;
    int qb = blockIdx.x;
    int qbase = qb * 64;
    const size_t base = ((size_t)b * 2048) * EMB + h * 64;

    for (int it = tid; it < 64 * 16; it += 256) {
        int r = it >> 4, d4 = (it & 15) << 2;
        float4 v = *(const float4*)(Q + base + (size_t)(qbase + r) * EMB + d4);
        *(float4*)&Qs[r * FA_PAD + d4] = v;
    }

    float m_i[4], l_i[4], acc[4][4];
    #pragma unroll
    for (int i = 0; i < 4; i++) {
        m_i[i] = -1e30f; l_i[i] = 0.f;
        #pragma unroll
        for (int j = 0; j < 4; j++) acc[i][j] = 0.f;
    }
    __syncthreads();

    const float scale = 0.03125f;  // 1/sqrt(1024)

    for (int t = 0; t <= qb; t++) {
        int kbase = t * 64;
        for (int it = tid; it < 64 * 16; it += 256) {
            int c = it >> 4, d4 = (it & 15) << 2;
            float4 kv = *(const float4*)(Kg + base + (size_t)(kbase + c) * EMB + d4);
            Kts[(d4 + 0) * FA_PAD + c] = kv.x;
            Kts[(d4 + 1) * FA_PAD + c] = kv.y;
            Kts[(d4 + 2) * FA_PAD + c] = kv.z;
            Kts[(d4 + 3) * FA_PAD + c] = kv.w;
            float4 vv = *(const float4*)(Vg + base + (size_t)(kbase + c) * EMB + d4);
            *(float4*)&Vs[c * FA_PAD + d4] = vv;
        }
        __syncthreads();

        float s[4][4];
        #pragma unroll
        for (int i = 0; i < 4; i++)
            #pragma unroll
            for (int j = 0; j < 4; j++) s[i][j] = 0.f;

        #pragma unroll 8
        for (int k = 0; k < 64; k++) {
            float a0 = Qs[(4 * ty + 0) * FA_PAD + k];
            float a1 = Qs[(4 * ty + 1) * FA_PAD + k];
            float a2 = Qs[(4 * ty + 2) * FA_PAD + k];
            float a3 = Qs[(4 * ty + 3) * FA_PAD + k];
            float4 kb4 = *(const float4*)&Kts[k * FA_PAD + 4 * tx];
            s[0][0] += a0 * kb4.x; s[0][1] += a0 * kb4.y; s[0][2] += a0 * kb4.z; s[0][3] += a0 * kb4.w;
            s[1][0] += a1 * kb4.x; s[1][1] += a1 * kb4.y; s[1][2] += a1 * kb4.z; s[1][3] += a1 * kb4.w;
            s[2][0] += a2 * kb4.x; s[2][1] += a2 * kb4.y; s[2][2] += a2 * kb4.z; s[2][3] += a2 * kb4.w;
            s[3][0] += a3 * kb4.x; s[3][1] += a3 * kb4.y; s[3][2] += a3 * kb4.z; s[3][3] += a3 * kb4.w;
        }

        bool diag = (t == qb);
        #pragma unroll
        for (int i = 0; i < 4; i++) {
            int r = 4 * ty + i;
            #pragma unroll
            for (int j = 0; j < 4; j++) {
                s[i][j] *= scale;
                if (diag && (kbase + 4 * tx + j) > (qbase + r)) s[i][j] = -1e30f;
            }
        }

        #pragma unroll
        for (int i = 0; i < 4; i++) {
            float tmax = fmaxf(fmaxf(s[i][0], s[i][1]), fmaxf(s[i][2], s[i][3]));
            #pragma unroll
            for (int off = 8; off > 0; off >>= 1)
                tmax = fmaxf(tmax, __shfl_xor_sync(0xffffffffu, tmax, off));
            float mnew = fmaxf(m_i[i], tmax);
            float alpha = __expf(m_i[i] - mnew);
            float p0 = __expf(s[i][0] - mnew);
            float p1 = __expf(s[i][1] - mnew);
            float p2 = __expf(s[i][2] - mnew);
            float p3 = __expf(s[i][3] - mnew);
            float rs = p0 + p1 + p2 + p3;
            #pragma unroll
            for (int off = 8; off > 0; off >>= 1)
                rs += __shfl_xor_sync(0xffffffffu, rs, off);
            l_i[i] = l_i[i] * alpha + rs;
            m_i[i] = mnew;
            #pragma unroll
            for (int j = 0; j < 4; j++) acc[i][j] *= alpha;
            float4 p4; p4.x = p0; p4.y = p1; p4.z = p2; p4.w = p3;
            *(float4*)&Ps[(4 * ty + i) * FA_PAD + 4 * tx] = p4;
        }
        __syncthreads();

        #pragma unroll 8
        for (int k = 0; k < 64; k++) {
            float a0 = Ps[(4 * ty + 0) * FA_PAD + k];
            float a1 = Ps[(4 * ty + 1) * FA_PAD + k];
            float a2 = Ps[(4 * ty + 2) * FA_PAD + k];
            float a3 = Ps[(4 * ty + 3) * FA_PAD + k];
            float4 v4 = *(const float4*)&Vs[k * FA_PAD + 4 * tx];
            acc[0][0] += a0 * v4.x; acc[0][1] += a0 * v4.y; acc[0][2] += a0 * v4.z; acc[0][3] += a0 * v4.w;
            acc[1][0] += a1 * v4.x; acc[1][1] += a1 * v4.y; acc[1][2] += a1 * v4.z; acc[1][3] += a1 * v4.w;
            acc[2][0] += a2 * v4.x; acc[2][1] += a2 * v4.y; acc[2][2] += a2 * v4.z; acc[2][3] += a2 * v4.w;
            acc[3][0] += a3 * v4.x; acc[3][1] += a3 * v4.y; acc[3][2] += a3 * v4.z; acc[3][3] += a3 * v4.w;
        }
        __syncthreads();
    }

    #pragma unroll
    for (int i = 0; i < 4; i++) {
        float inv = 1.0f / l_i[i];
        float4 o4;
        o4.x = tf32_rna(acc[i][0] * inv); o4.y = tf32_rna(acc[i][1] * inv);
        o4.z = tf32_rna(acc[i][2] * inv); o4.w = tf32_rna(acc[i][3] * inv);
        *(float4*)(O + base + (size_t)(qbase + 4 * ty + i) * EMB + 4 * tx) = o4;
    }
}

// ---------------- launch ----------------------------------------------------
extern "C" void kernel_launch(void* const* d_in, const int* in_sizes, int n_in,
                              void* d_out, int out_size)
{
    const float* x   = (const float*)d_in[0];
    const float* Wq  = (const float*)d_in[1];
    const float* bq  = (const float*)d_in[2];
    const float* Wk  = (const float*)d_in[3];
    const float* bk  = (const float*)d_in[4];
    const float* Wv  = (const float*)d_in[5];
    const float* bv  = (const float*)d_in[6];
    const float* Wo  = (const float*)d_in[7];
    const float* W1  = (const float*)d_in[8];
    const float* b1  = (const float*)d_in[9];
    const float* W2  = (const float*)d_in[10];
    const float* b2  = (const float*)d_in[11];
    const float* g1  = (const float*)d_in[12];
    const float* be1 = (const float*)d_in[13];
    const float* g2  = (const float*)d_in[14];
    const float* be2 = (const float*)d_in[15];
    float* out = (float*)d_out;

    float *ln1, *qb2, *kb2, *vb2, *zb, *hb, *ln2b, *ffb;
    float *wqr, *wkr, *wvr, *wor, *w1r, *w2r;
    cudaGetSymbolAddress((void**)&ln1,  g_ln1);
    cudaGetSymbolAddress((void**)&qb2,  g_q);
    cudaGetSymbolAddress((void**)&kb2,  g_k);
    cudaGetSymbolAddress((void**)&vb2,  g_v);
    cudaGetSymbolAddress((void**)&zb,   g_z);
    cudaGetSymbolAddress((void**)&hb,   g_h);
    cudaGetSymbolAddress((void**)&ln2b, g_ln2);
    cudaGetSymbolAddress((void**)&ffb,  g_ff);
    cudaGetSymbolAddress((void**)&wqr,  g_wq);
    cudaGetSymbolAddress((void**)&wkr,  g_wk);
    cudaGetSymbolAddress((void**)&wvr,  g_wv);
    cudaGetSymbolAddress((void**)&wor,  g_wo);
    cudaGetSymbolAddress((void**)&w1r,  g_w1);
    cudaGetSymbolAddress((void**)&w2r,  g_w2);

    // allow big dynamic smem on the GEMM variants
    cudaFuncSetAttribute(gemm_tf32_kernel<true,  false, false, false>,
                         cudaFuncAttributeMaxDynamicSharedMemorySize, GEMM_SMEM);
    cudaFuncSetAttribute(gemm_tf32_kernel<false, false, true,  false>,
                         cudaFuncAttributeMaxDynamicSharedMemorySize, GEMM_SMEM);
    cudaFuncSetAttribute(gemm_tf32_kernel<true,  true,  false, true >,
                         cudaFuncAttributeMaxDynamicSharedMemorySize, GEMM_SMEM);
    cudaFuncSetAttribute(gemm_tf32_kernel<true,  false, true,  false>,
                         cudaFuncAttributeMaxDynamicSharedMemorySize, GEMM_SMEM);

    // 0) round weights to tf32 once per launch
    {
        int n4a = EMB * EMB / 4;
        round_copy_kernel<<<(n4a + 255) / 256, 256>>>(Wq, wqr, n4a);
        round_copy_kernel<<<(n4a + 255) / 256, 256>>>(Wk, wkr, n4a);
        round_copy_kernel<<<(n4a + 255) / 256, 256>>>(Wv, wvr, n4a);
        round_copy_kernel<<<(n4a + 255) / 256, 256>>>(Wo, wor, n4a);
        int n4b = EMB * FFD / 4;
        round_copy_kernel<<<(n4b + 255) / 256, 256>>>(W1, w1r, n4b);
        round_copy_kernel<<<(n4b + 255) / 256, 256>>>(W2, w2r, n4b);
    }

    // 1) ln1 = round(LN(x))
    layernorm_kernel<<<NTOK, 256>>>(x, g1, be1, ln1);

    // 2) Q, K, V projections (bias fused)
    gemm_tf32_kernel<true, false, false, false><<<dim3(EMB / 128, NTOK / 128), 256, GEMM_SMEM>>>(
        ln1, wqr, bq, nullptr, qb2, NTOK, EMB, EMB);
    gemm_tf32_kernel<true, false, false, false><<<dim3(EMB / 128, NTOK / 128), 256, GEMM_SMEM>>>(
        ln1, wkr, bk, nullptr, kb2, NTOK, EMB, EMB);
    gemm_tf32_kernel<true, false, false, false><<<dim3(EMB / 128, NTOK / 128), 256, GEMM_SMEM>>>(
        ln1, wvr, bv, nullptr, vb2, NTOK, EMB, EMB);

    // 3) causal flash attention (fp32 math, rounded output)
    cudaFuncSetAttribute(flash_kernel, cudaFuncAttributeMaxDynamicSharedMemorySize,
                         4 * 64 * FA_PAD * sizeof(float));
    flash_kernel<<<dim3(32, 32), 256, 4 * 64 * FA_PAD * sizeof(float)>>>(qb2, kb2, vb2, zb);

    // 4) h = x + z @ Wo
    gemm_tf32_kernel<false, false, true, false><<<dim3(EMB / 128, NTOK / 128), 256, GEMM_SMEM>>>(
        zb, wor, nullptr, x, hb, NTOK, EMB, EMB);

    // 5) ln2 = round(LN(h))
    layernorm_kernel<<<NTOK, 256>>>(hb, g2, be2, ln2b);

    // 6) ff = round(gelu(ln2 @ W1 + b1))
    gemm_tf32_kernel<true, true, false, true><<<dim3(FFD / 128, NTOK / 128), 256, GEMM_SMEM>>>(
        ln2b, w1r, b1, nullptr, ffb, NTOK, FFD, EMB);

    // 7) out = h + ff @ W2 + b2
    gemm_tf32_kernel<true, false, true, false><<<dim3(EMB / 128, NTOK / 128), 256, GEMM_SMEM>>>(
        ffb, w2r, b2, hb, out, NTOK, EMB, FFD);
}

// round 5
// speedup vs baseline: 3.5821x; 2.2905x over previous
#include <cuda_runtime.h>
#include <math.h>

// ---------------- scratch (device globals; no allocation allowed) ----------
#define NTOK 4096            // B*S = 2*2048
#define EMB  1024
#define FFD  4096

__device__ float g_ln1[NTOK * EMB];
__device__ float g_q  [NTOK * EMB];
__device__ float g_k  [NTOK * EMB];
__device__ float g_v  [NTOK * EMB];
__device__ float g_z  [NTOK * EMB];
__device__ float g_h  [NTOK * EMB];
__device__ float g_ln2[NTOK * EMB];
__device__ float g_ff [NTOK * FFD];
// tf32-rounded weight copies
__device__ float g_wq[EMB * EMB];
__device__ float g_wk[EMB * EMB];
__device__ float g_wv[EMB * EMB];
__device__ float g_wo[EMB * EMB];
__device__ float g_w1[EMB * FFD];
__device__ float g_w2[FFD * EMB];

// ---------------- helpers ---------------------------------------------------
__device__ __forceinline__ float tf32_rna(float f) {
    unsigned u;
    asm("cvt.rna.tf32.f32 %0, %1;" : "=r"(u) : "f"(f));
    return __uint_as_float(u);
}

#define CP_ASYNC16(dst_u32, src_ptr) \
    asm volatile("cp.async.cg.shared.global [%0], [%1], 16;" :: "r"(dst_u32), "l"(src_ptr))
#define CP_COMMIT() asm volatile("cp.async.commit_group;")
#define CP_WAIT1()  asm volatile("cp.async.wait_group 1;")
#define CP_WAIT0()  asm volatile("cp.async.wait_group 0;")

#define MMA_TF32(d0,d1,d2,d3, a0,a1,a2,a3, b0,b1) \
    asm volatile( \
        "mma.sync.aligned.m16n8k8.row.col.f32.tf32.tf32.f32 " \
        "{%0,%1,%2,%3}, {%4,%5,%6,%7}, {%8,%9}, {%0,%1,%2,%3};" \
        : "+f"(d0), "+f"(d1), "+f"(d2), "+f"(d3) \
        : "r"(a0), "r"(a1), "r"(a2), "r"(a3), "r"(b0), "r"(b1))

// ---------------- round-copy (weights -> tf32-rounded copies) ---------------
__global__ void __launch_bounds__(256) round_copy_kernel(
    const float* __restrict__ in, float* __restrict__ out, int n4)
{
    int i = blockIdx.x * blockDim.x + threadIdx.x;
    if (i < n4) {
        float4 v = ((const float4*)in)[i];
        v.x = tf32_rna(v.x); v.y = tf32_rna(v.y);
        v.z = tf32_rna(v.z); v.w = tf32_rna(v.w);
        ((float4*)out)[i] = v;
    }
}

// ---------------- LayerNorm (output rounded to tf32: feeds GEMMs only) ------
__global__ void __launch_bounds__(256) layernorm_kernel(
    const float* __restrict__ x, const float* __restrict__ g,
    const float* __restrict__ b, float* __restrict__ out)
{
    int row = blockIdx.x;
    int tid = threadIdx.x;
    const float4* xr = (const float4*)(x + (size_t)row * EMB);
    float4 v = xr[tid];
    float s  = v.x + v.y + v.z + v.w;
    float ss = v.x*v.x + v.y*v.y + v.z*v.z + v.w*v.w;
    #pragma unroll
    for (int off = 16; off > 0; off >>= 1) {
        s  += __shfl_xor_sync(0xffffffffu, s,  off);
        ss += __shfl_xor_sync(0xffffffffu, ss, off);
    }
    __shared__ float sbuf[8], ssbuf[8], red[2];
    int warp = tid >> 5, lane = tid & 31;
    if (lane == 0) { sbuf[warp] = s; ssbuf[warp] = ss; }
    __syncthreads();
    if (tid < 32) {
        float a = (tid < 8) ? sbuf[tid]  : 0.f;
        float c = (tid < 8) ? ssbuf[tid] : 0.f;
        #pragma unroll
        for (int off = 4; off > 0; off >>= 1) {
            a += __shfl_xor_sync(0xffffffffu, a, off);
            c += __shfl_xor_sync(0xffffffffu, c, off);
        }
        if (tid == 0) { red[0] = a; red[1] = c; }
    }
    __syncthreads();
    float mu   = red[0] * (1.0f / EMB);
    float var  = red[1] * (1.0f / EMB) - mu * mu;
    float rstd = rsqrtf(var + 1e-5f);
    float4 gg = ((const float4*)g)[tid];
    float4 bb = ((const float4*)b)[tid];
    float4 o;
    o.x = tf32_rna((v.x - mu) * rstd * gg.x + bb.x);
    o.y = tf32_rna((v.y - mu) * rstd * gg.y + bb.y);
    o.z = tf32_rna((v.z - mu) * rstd * gg.z + bb.z);
    o.w = tf32_rna((v.w - mu) * rstd * gg.w + bb.w);
    ((float4*)(out + (size_t)row * EMB))[tid] = o;
}

// ---------------- TF32 tensor-core GEMM -------------------------------------
#define APITCH 36
#define BPITCH 136
#define AS_ELEMS (128 * APITCH)
#define BS_ELEMS (32  * BPITCH)
#define GEMM_SMEM ((2 * AS_ELEMS + 2 * BS_ELEMS) * 4)

template<bool BIAS, bool GELU, bool RES, bool ROUND>
__global__ void __launch_bounds__(256, 2) gemm_tf32_kernel(
    const float* __restrict__ A, const float* __restrict__ W,
    const float* __restrict__ bias, const float* __restrict__ res,
    float* __restrict__ C, int M, int N, int K)
{
    extern __shared__ float sm[];
    float* As = sm;                      // [2][128][APITCH]
    float* Bs = sm + 2 * AS_ELEMS;       // [2][32][BPITCH]

    const int tid  = threadIdx.x;
    const int lane = tid & 31;
    const int warp = tid >> 5;
    const int wm   = warp & 3;
    const int wn   = warp >> 2;
    const int lm   = lane >> 2;
    const int lk   = lane & 3;
    const int m0 = blockIdx.y * 128, n0 = blockIdx.x * 128;

    unsigned as_base = (unsigned)__cvta_generic_to_shared(As);
    unsigned bs_base = (unsigned)__cvta_generic_to_shared(Bs);

    float acc[2][8][4];
    #pragma unroll
    for (int i = 0; i < 2; i++)
        #pragma unroll
        for (int j = 0; j < 8; j++)
            #pragma unroll
            for (int q = 0; q < 4; q++) acc[i][j][q] = 0.f;

    const int T = K / 32;

    {
        #pragma unroll
        for (int l = 0; l < 4; l++) {
            int idx = tid + l * 256;
            int row = idx >> 3, kc = (idx & 7) << 2;
            const float* src = A + (size_t)(m0 + row) * K + kc;
            unsigned dst = as_base + (unsigned)((row * APITCH + kc) * 4);
            CP_ASYNC16(dst, src);
        }
        #pragma unroll
        for (int l = 0; l < 4; l++) {
            int idx = tid + l * 256;
            int kr = idx >> 5, nc = (idx & 31) << 2;
            const float* src = W + (size_t)kr * N + n0 + nc;
            unsigned dst = bs_base + (unsigned)((kr * BPITCH + nc) * 4);
            CP_ASYNC16(dst, src);
        }
        CP_COMMIT();
    }

    for (int it = 0; it < T; it++) {
        if (it + 1 < T) {
            int st = (it + 1) & 1;
            int k0 = (it + 1) * 32;
            #pragma unroll
            for (int l = 0; l < 4; l++) {
                int idx = tid + l * 256;
                int row = idx >> 3, kc = (idx & 7) << 2;
                const float* src = A + (size_t)(m0 + row) * K + k0 + kc;
                unsigned dst = as_base + (unsigned)((st * AS_ELEMS + row * APITCH + kc) * 4);
                CP_ASYNC16(dst, src);
            }
            #pragma unroll
            for (int l = 0; l < 4; l++) {
                int idx = tid + l * 256;
                int kr = idx >> 5, nc = (idx & 31) << 2;
                const float* src = W + (size_t)(k0 + kr) * N + n0 + nc;
                unsigned dst = bs_base + (unsigned)((st * BS_ELEMS + kr * BPITCH + nc) * 4);
                CP_ASYNC16(dst, src);
            }
            CP_COMMIT();
            CP_WAIT1();
        } else {
            CP_WAIT0();
        }
        __syncthreads();

        const int st = it & 1;
        const float* Asb = As + st * AS_ELEMS;
        const float* Bsb = Bs + st * BS_ELEMS;

        #pragma unroll
        for (int kk = 0; kk < 4; kk++) {
            const int kb = kk * 8;
            unsigned b[8][2], a[2][4];
            #pragma unroll
            for (int jn = 0; jn < 8; jn++) {
                int col = wn * 64 + jn * 8 + lm;
                b[jn][0] = __float_as_uint(Bsb[(kb + lk) * BPITCH + col]);
                b[jn][1] = __float_as_uint(Bsb[(kb + 4 + lk) * BPITCH + col]);
            }
            #pragma unroll
            for (int im = 0; im < 2; im++) {
                int row = wm * 32 + im * 16 + lm;
                a[im][0] = __float_as_uint(Asb[row       * APITCH + kb + lk]);
                a[im][1] = __float_as_uint(Asb[(row + 8) * APITCH + kb + lk]);
                a[im][2] = __float_as_uint(Asb[row       * APITCH + kb + 4 + lk]);
                a[im][3] = __float_as_uint(Asb[(row + 8) * APITCH + kb + 4 + lk]);
            }
            #pragma unroll
            for (int im = 0; im < 2; im++)
                #pragma unroll
                for (int jn = 0; jn < 8; jn++)
                    MMA_TF32(acc[im][jn][0], acc[im][jn][1], acc[im][jn][2], acc[im][jn][3],
                             a[im][0], a[im][1], a[im][2], a[im][3],
                             b[jn][0], b[jn][1]);
        }
        __syncthreads();
    }

    #pragma unroll
    for (int im = 0; im < 2; im++) {
        int r0 = m0 + wm * 32 + im * 16 + lm;
        #pragma unroll
        for (int jn = 0; jn < 8; jn++) {
            int c = n0 + wn * 64 + jn * 8 + lk * 2;
            float v[4] = { acc[im][jn][0], acc[im][jn][1],
                           acc[im][jn][2], acc[im][jn][3] };
            if (BIAS) {
                float2 bq = *(const float2*)(bias + c);
                v[0] += bq.x; v[1] += bq.y; v[2] += bq.x; v[3] += bq.y;
            }
            if (GELU) {
                #pragma unroll
                for (int q = 0; q < 4; q++)
                    v[q] = 0.5f * v[q] * (1.0f + erff(v[q] * 0.70710678118654752f));
            }
            if (RES) {
                float2 rlo = *(const float2*)(res + (size_t)r0 * N + c);
                float2 rhi = *(const float2*)(res + (size_t)(r0 + 8) * N + c);
                v[0] += rlo.x; v[1] += rlo.y; v[2] += rhi.x; v[3] += rhi.y;
            }
            if (ROUND) {
                #pragma unroll
                for (int q = 0; q < 4; q++) v[q] = tf32_rna(v[q]);
            }
            float2 lo; lo.x = v[0]; lo.y = v[1];
            float2 hi; hi.x = v[2]; hi.y = v[3];
            *(float2*)(C + (size_t)r0 * N + c)       = lo;
            *(float2*)(C + (size_t)(r0 + 8) * N + c) = hi;
        }
    }
}

// ---------------- Flash attention, tensor-core tf32 -------------------------
// BQ=BKV=64, D=64. 128 threads = 4 warps; warp tile 16 q-rows x 64 kv/d cols.
// Q/K/P smem pitch 68 (=4 mod 32: conflict-free (g,t4) fragment reads),
// V pitch 72 (=8 mod 32: conflict-free (t4-row, g-col) B-fragment reads).
#define QP 68
#define KP 68
#define VP 72
#define PP 68
#define FLASH_SMEM ((64 * (QP + KP + VP + PP)) * 4)

__global__ void __launch_bounds__(128) flash_tc_kernel(
    const float* __restrict__ Q, const float* __restrict__ Kg,
    const float* __restrict__ Vg, float* __restrict__ O)
{
    extern __shared__ float smfa[];
    float* Qs = smfa;              // [64][QP]  (q, d)
    float* Ks = Qs + 64 * QP;      // [64][KP]  (kv, d)
    float* Vs = Ks + 64 * KP;      // [64][VP]  (kv, d)
    float* Ps = Vs + 64 * VP;      // [64][PP]  (q, kv)

    const int tid  = threadIdx.x;
    const int lane = tid & 31;
    const int warp = tid >> 5;          // 0..3 -> q rows [warp*16, +16)
    const int g    = lane >> 2;         // groupID 0..7
    const int t4   = lane & 3;          // threadID-in-group 0..3

    const int bh = blockIdx.y;
    const int b = bh >> 4, h = bh & 15;
    const int qb = blockIdx.x;
    const int qbase = qb * 64;
    const size_t base = ((size_t)b * 2048) * EMB + h * 64;

    // load Q tile (tf32-rounded)
    #pragma unroll
    for (int l = 0; l < 8; l++) {
        int idx = tid + l * 128;
        int r = idx >> 4, d4 = (idx & 15) << 2;
        float4 v = *(const float4*)(Q + base + (size_t)(qbase + r) * EMB + d4);
        v.x = tf32_rna(v.x); v.y = tf32_rna(v.y);
        v.z = tf32_rna(v.z); v.w = tf32_rna(v.w);
        *(float4*)&Qs[r * QP + d4] = v;
    }

    float m0 = -1e30f, m1 = -1e30f, l0 = 0.f, l1 = 0.f;
    float acc[8][4];
    #pragma unroll
    for (int n = 0; n < 8; n++)
        #pragma unroll
        for (int q = 0; q < 4; q++) acc[n][q] = 0.f;

    const int row0l = warp * 16 + g;        // local q row (and +8)
    const int grow0 = qbase + row0l;
    const int grow1 = grow0 + 8;
    const float scale = 0.03125f;           // 1/sqrt(1024)

    __syncthreads();

    for (int t = 0; t <= qb; t++) {
        const int kvbase = t * 64;
        // load K, V tiles (tf32-rounded)
        #pragma unroll
        for (int l = 0; l < 8; l++) {
            int idx = tid + l * 128;
            int c = idx >> 4, d4 = (idx & 15) << 2;
            float4 kv = *(const float4*)(Kg + base + (size_t)(kvbase + c) * EMB + d4);
            kv.x = tf32_rna(kv.x); kv.y = tf32_rna(kv.y);
            kv.z = tf32_rna(kv.z); kv.w = tf32_rna(kv.w);
            *(float4*)&Ks[c * KP + d4] = kv;
            float4 vv = *(const float4*)(Vg + base + (size_t)(kvbase + c) * EMB + d4);
            vv.x = tf32_rna(vv.x); vv.y = tf32_rna(vv.y);
            vv.z = tf32_rna(vv.z); vv.w = tf32_rna(vv.w);
            *(float4*)&Vs[c * VP + d4] = vv;
        }
        __syncthreads();

        // ---- S = Q @ K^T  (warp: 16 rows x 64 cols = 8 n-tiles) ----
        float s[8][4];
        #pragma unroll
        for (int n = 0; n < 8; n++)
            #pragma unroll
            for (int q = 0; q < 4; q++) s[n][q] = 0.f;

        #pragma unroll
        for (int ks = 0; ks < 8; ks++) {
            const int kb = ks * 8;
            unsigned a0 = __float_as_uint(Qs[(row0l    ) * QP + kb + t4]);
            unsigned a1 = __float_as_uint(Qs[(row0l + 8) * QP + kb + t4]);
            unsigned a2 = __float_as_uint(Qs[(row0l    ) * QP + kb + 4 + t4]);
            unsigned a3 = __float_as_uint(Qs[(row0l + 8) * QP + kb + 4 + t4]);
            #pragma unroll
            for (int n = 0; n < 8; n++) {
                unsigned b0 = __float_as_uint(Ks[(n * 8 + g) * KP + kb + t4]);
                unsigned b1 = __float_as_uint(Ks[(n * 8 + g) * KP + kb + 4 + t4]);
                MMA_TF32(s[n][0], s[n][1], s[n][2], s[n][3], a0, a1, a2, a3, b0, b1);
            }
        }

        // ---- scale + causal mask ----
        const bool diag = (t == qb);
        #pragma unroll
        for (int n = 0; n < 8; n++) {
            int c0 = kvbase + n * 8 + 2 * t4;
            s[n][0] *= scale; s[n][1] *= scale;
            s[n][2] *= scale; s[n][3] *= scale;
            if (diag) {
                if (c0     > grow0) s[n][0] = -1e30f;
                if (c0 + 1 > grow0) s[n][1] = -1e30f;
                if (c0     > grow1) s[n][2] = -1e30f;
                if (c0 + 1 > grow1) s[n][3] = -1e30f;
            }
        }

        // ---- online softmax (rows row0l, row0l+8) ----
        float mx0 = -1e30f, mx1 = -1e30f;
        #pragma unroll
        for (int n = 0; n < 8; n++) {
            mx0 = fmaxf(mx0, fmaxf(s[n][0], s[n][1]));
            mx1 = fmaxf(mx1, fmaxf(s[n][2], s[n][3]));
        }
        mx0 = fmaxf(mx0, __shfl_xor_sync(0xffffffffu, mx0, 1));
        mx0 = fmaxf(mx0, __shfl_xor_sync(0xffffffffu, mx0, 2));
        mx1 = fmaxf(mx1, __shfl_xor_sync(0xffffffffu, mx1, 1));
        mx1 = fmaxf(mx1, __shfl_xor_sync(0xffffffffu, mx1, 2));

        float mn0 = fmaxf(m0, mx0), mn1 = fmaxf(m1, mx1);
        float al0 = __expf(m0 - mn0), al1 = __expf(m1 - mn1);
        m0 = mn0; m1 = mn1;

        float rs0 = 0.f, rs1 = 0.f;
        #pragma unroll
        for (int n = 0; n < 8; n++) {
            s[n][0] = __expf(s[n][0] - mn0);
            s[n][1] = __expf(s[n][1] - mn0);
            s[n][2] = __expf(s[n][2] - mn1);
            s[n][3] = __expf(s[n][3] - mn1);
            rs0 += s[n][0] + s[n][1];
            rs1 += s[n][2] + s[n][3];
        }
        rs0 += __shfl_xor_sync(0xffffffffu, rs0, 1);
        rs0 += __shfl_xor_sync(0xffffffffu, rs0, 2);
        rs1 += __shfl_xor_sync(0xffffffffu, rs1, 1);
        rs1 += __shfl_xor_sync(0xffffffffu, rs1, 2);
        l0 = l0 * al0 + rs0;
        l1 = l1 * al1 + rs1;

        #pragma unroll
        for (int n = 0; n < 8; n++) {
            acc[n][0] *= al0; acc[n][1] *= al0;
            acc[n][2] *= al1; acc[n][3] *= al1;
            // store P (tf32-rounded) — each warp writes only its own 16 rows
            float2 plo; plo.x = tf32_rna(s[n][0]); plo.y = tf32_rna(s[n][1]);
            float2 phi; phi.x = tf32_rna(s[n][2]); phi.y = tf32_rna(s[n][3]);
            *(float2*)&Ps[(row0l    ) * PP + n * 8 + 2 * t4] = plo;
            *(float2*)&Ps[(row0l + 8) * PP + n * 8 + 2 * t4] = phi;
        }
        __syncwarp();

        // ---- acc += P @ V ----
        #pragma unroll
        for (int ks = 0; ks < 8; ks++) {
            const int kb = ks * 8;
            unsigned a0 = __float_as_uint(Ps[(row0l    ) * PP + kb + t4]);
            unsigned a1 = __float_as_uint(Ps[(row0l + 8) * PP + kb + t4]);
            unsigned a2 = __float_as_uint(Ps[(row0l    ) * PP + kb + 4 + t4]);
            unsigned a3 = __float_as_uint(Ps[(row0l + 8) * PP + kb + 4 + t4]);
            #pragma unroll
            for (int n = 0; n < 8; n++) {
                unsigned b0 = __float_as_uint(Vs[(kb + t4    ) * VP + n * 8 + g]);
                unsigned b1 = __float_as_uint(Vs[(kb + 4 + t4) * VP + n * 8 + g]);
                MMA_TF32(acc[n][0], acc[n][1], acc[n][2], acc[n][3], a0, a1, a2, a3, b0, b1);
            }
        }
        __syncthreads();
    }

    // ---- write O = acc / l (tf32-rounded: feeds Wo GEMM) ----
    float inv0 = 1.0f / l0, inv1 = 1.0f / l1;
    #pragma unroll
    for (int n = 0; n < 8; n++) {
        int c = n * 8 + 2 * t4;
        float2 lo; lo.x = tf32_rna(acc[n][0] * inv0); lo.y = tf32_rna(acc[n][1] * inv0);
        float2 hi; hi.x = tf32_rna(acc[n][2] * inv1); hi.y = tf32_rna(acc[n][3] * inv1);
        *(float2*)(O + base + (size_t)grow0 * EMB + c) = lo;
        *(float2*)(O + base + (size_t)grow1 * EMB + c) = hi;
    }
}

// ---------------- launch ----------------------------------------------------
extern "C" void kernel_launch(void* const* d_in, const int* in_sizes, int n_in,
                              void* d_out, int out_size)
{
    const float* x   = (const float*)d_in[0];
    const float* Wq  = (const float*)d_in[1];
    const float* bq  = (const float*)d_in[2];
    const float* Wk  = (const float*)d_in[3];
    const float* bk  = (const float*)d_in[4];
    const float* Wv  = (const float*)d_in[5];
    const float* bv  = (const float*)d_in[6];
    const float* Wo  = (const float*)d_in[7];
    const float* W1  = (const float*)d_in[8];
    const float* b1  = (const float*)d_in[9];
    const float* W2  = (const float*)d_in[10];
    const float* b2  = (const float*)d_in[11];
    const float* g1  = (const float*)d_in[12];
    const float* be1 = (const float*)d_in[13];
    const float* g2  = (const float*)d_in[14];
    const float* be2 = (const float*)d_in[15];
    float* out = (float*)d_out;

    float *ln1, *qb2, *kb2, *vb2, *zb, *hb, *ln2b, *ffb;
    float *wqr, *wkr, *wvr, *wor, *w1r, *w2r;
    cudaGetSymbolAddress((void**)&ln1,  g_ln1);
    cudaGetSymbolAddress((void**)&qb2,  g_q);
    cudaGetSymbolAddress((void**)&kb2,  g_k);
    cudaGetSymbolAddress((void**)&vb2,  g_v);
    cudaGetSymbolAddress((void**)&zb,   g_z);
    cudaGetSymbolAddress((void**)&hb,   g_h);
    cudaGetSymbolAddress((void**)&ln2b, g_ln2);
    cudaGetSymbolAddress((void**)&ffb,  g_ff);
    cudaGetSymbolAddress((void**)&wqr,  g_wq);
    cudaGetSymbolAddress((void**)&wkr,  g_wk);
    cudaGetSymbolAddress((void**)&wvr,  g_wv);
    cudaGetSymbolAddress((void**)&wor,  g_wo);
    cudaGetSymbolAddress((void**)&w1r,  g_w1);
    cudaGetSymbolAddress((void**)&w2r,  g_w2);

    cudaFuncSetAttribute(gemm_tf32_kernel<true,  false, false, false>,
                         cudaFuncAttributeMaxDynamicSharedMemorySize, GEMM_SMEM);
    cudaFuncSetAttribute(gemm_tf32_kernel<false, false, true,  false>,
                         cudaFuncAttributeMaxDynamicSharedMemorySize, GEMM_SMEM);
    cudaFuncSetAttribute(gemm_tf32_kernel<true,  true,  false, true >,
                         cudaFuncAttributeMaxDynamicSharedMemorySize, GEMM_SMEM);
    cudaFuncSetAttribute(gemm_tf32_kernel<true,  false, true,  false>,
                         cudaFuncAttributeMaxDynamicSharedMemorySize, GEMM_SMEM);
    cudaFuncSetAttribute(flash_tc_kernel,
                         cudaFuncAttributeMaxDynamicSharedMemorySize, FLASH_SMEM);

    // 0) round weights to tf32 once per launch
    {
        int n4a = EMB * EMB / 4;
        round_copy_kernel<<<(n4a + 255) / 256, 256>>>(Wq, wqr, n4a);
        round_copy_kernel<<<(n4a + 255) / 256, 256>>>(Wk, wkr, n4a);
        round_copy_kernel<<<(n4a + 255) / 256, 256>>>(Wv, wvr, n4a);
        round_copy_kernel<<<(n4a + 255) / 256, 256>>>(Wo, wor, n4a);
        int n4b = EMB * FFD / 4;
        round_copy_kernel<<<(n4b + 255) / 256, 256>>>(W1, w1r, n4b);
        round_copy_kernel<<<(n4b + 255) / 256, 256>>>(W2, w2r, n4b);
    }

    // 1) ln1 = round(LN(x))
    layernorm_kernel<<<NTOK, 256>>>(x, g1, be1, ln1);

    // 2) Q, K, V projections (bias fused)
    gemm_tf32_kernel<true, false, false, false><<<dim3(EMB / 128, NTOK / 128), 256, GEMM_SMEM>>>(
        ln1, wqr, bq, nullptr, qb2, NTOK, EMB, EMB);
    gemm_tf32_kernel<true, false, false, false><<<dim3(EMB / 128, NTOK / 128), 256, GEMM_SMEM>>>(
        ln1, wkr, bk, nullptr, kb2, NTOK, EMB, EMB);
    gemm_tf32_kernel<true, false, false, false><<<dim3(EMB / 128, NTOK / 128), 256, GEMM_SMEM>>>(
        ln1, wvr, bv, nullptr, vb2, NTOK, EMB, EMB);

    // 3) causal flash attention (tensor-core tf32)
    flash_tc_kernel<<<dim3(32, 32), 128, FLASH_SMEM>>>(qb2, kb2, vb2, zb);

    // 4) h = x + z @ Wo
    gemm_tf32_kernel<false, false, true, false><<<dim3(EMB / 128, NTOK / 128), 256, GEMM_SMEM>>>(
        zb, wor, nullptr, x, hb, NTOK, EMB, EMB);

    // 5) ln2 = round(LN(h))
    layernorm_kernel<<<NTOK, 256>>>(hb, g2, be2, ln2b);

    // 6) ff = round(gelu(ln2 @ W1 + b1))
    gemm_tf32_kernel<true, true, false, true><<<dim3(FFD / 128, NTOK / 128), 256, GEMM_SMEM>>>(
        ln2b, w1r, b1, nullptr, ffb, NTOK, FFD, EMB);

    // 7) out = h + ff @ W2 + b2
    gemm_tf32_kernel<true, false, true, false><<<dim3(EMB / 128, NTOK / 128), 256, GEMM_SMEM>>>(
        ffb, w2r, b2, hb, out, NTOK, EMB, FFD);
}

// round 7
// speedup vs baseline: 3.8079x; 1.0630x over previous
#include <cuda_runtime.h>
#include <math.h>

// ---------------- scratch (device globals; no allocation allowed) ----------
#define NTOK 4096            // B*S = 2*2048
#define EMB  1024
#define FFD  4096
#define QKVN 3072

__device__ float g_ln1 [NTOK * EMB];
__device__ float g_qkv [NTOK * QKVN];
__device__ float g_z   [NTOK * EMB];
__device__ float g_h   [NTOK * EMB];
__device__ float g_ln2 [NTOK * EMB];
__device__ float g_ff  [NTOK * FFD];
// tf32-rounded weights
__device__ float g_wqkv[EMB * QKVN];
__device__ float g_bqkv[QKVN];
__device__ float g_wo  [EMB * EMB];
__device__ float g_w1  [EMB * FFD];
__device__ float g_w2  [FFD * EMB];

// ---------------- helpers ---------------------------------------------------
__device__ __forceinline__ float tf32_rna(float f) {
    unsigned u;
    asm("cvt.rna.tf32.f32 %0, %1;" : "=r"(u) : "f"(f));
    return __uint_as_float(u);
}

#define CP_ASYNC16(dst_u32, src_ptr) \
    asm volatile("cp.async.cg.shared.global [%0], [%1], 16;" :: "r"(dst_u32), "l"(src_ptr))
#define CP_COMMIT() asm volatile("cp.async.commit_group;")
#define CP_WAIT1()  asm volatile("cp.async.wait_group 1;")
#define CP_WAIT0()  asm volatile("cp.async.wait_group 0;")

#define MMA_TF32(d0,d1,d2,d3, a0,a1,a2,a3, b0,b1) \
    asm volatile( \
        "mma.sync.aligned.m16n8k8.row.col.f32.tf32.tf32.f32 " \
        "{%0,%1,%2,%3}, {%4,%5,%6,%7}, {%8,%9}, {%0,%1,%2,%3};" \
        : "+f"(d0), "+f"(d1), "+f"(d2), "+f"(d3) \
        : "r"(a0), "r"(a1), "r"(a2), "r"(a3), "r"(b0), "r"(b1))

// ---------------- weight prep ------------------------------------------------
__global__ void __launch_bounds__(256) round_copy_kernel(
    const float* __restrict__ in, float* __restrict__ out, int n4)
{
    int i = blockIdx.x * blockDim.x + threadIdx.x;
    if (i < n4) {
        float4 v = ((const float4*)in)[i];
        v.x = tf32_rna(v.x); v.y = tf32_rna(v.y);
        v.z = tf32_rna(v.z); v.w = tf32_rna(v.w);
        ((float4*)out)[i] = v;
    }
}

// pack Wq|Wk|Wv -> [EMB][3072], tf32-rounded
__global__ void __launch_bounds__(256) pack_qkv_w_kernel(
    const float* __restrict__ Wq, const float* __restrict__ Wk,
    const float* __restrict__ Wv, float* __restrict__ out)
{
    int i4 = blockIdx.x * blockDim.x + threadIdx.x;
    if (i4 >= EMB * QKVN / 4) return;
    int c4 = i4 % (QKVN / 4);
    int k  = i4 / (QKVN / 4);
    int n  = c4 * 4;
    const float* src;
    int off;
    if (n < EMB)            { src = Wq; off = k * EMB + n; }
    else if (n < 2 * EMB)   { src = Wk; off = k * EMB + n - EMB; }
    else                    { src = Wv; off = k * EMB + n - 2 * EMB; }
    float4 v = *(const float4*)(src + off);
    v.x = tf32_rna(v.x); v.y = tf32_rna(v.y);
    v.z = tf32_rna(v.z); v.w = tf32_rna(v.w);
    ((float4*)out)[i4] = v;
}

__global__ void __launch_bounds__(256) pack_qkv_b_kernel(
    const float* __restrict__ bq, const float* __restrict__ bk,
    const float* __restrict__ bv, float* __restrict__ out)
{
    int i = blockIdx.x * blockDim.x + threadIdx.x;
    if (i >= QKVN) return;
    out[i] = (i < EMB) ? bq[i] : (i < 2 * EMB) ? bk[i - EMB] : bv[i - 2 * EMB];
}

// ---------------- LayerNorm (tf32-rounded output) ---------------------------
__global__ void __launch_bounds__(256) layernorm_kernel(
    const float* __restrict__ x, const float* __restrict__ g,
    const float* __restrict__ b, float* __restrict__ out)
{
    int row = blockIdx.x;
    int tid = threadIdx.x;
    const float4* xr = (const float4*)(x + (size_t)row * EMB);
    float4 v = xr[tid];
    float s  = v.x + v.y + v.z + v.w;
    float ss = v.x*v.x + v.y*v.y + v.z*v.z + v.w*v.w;
    #pragma unroll
    for (int off = 16; off > 0; off >>= 1) {
        s  += __shfl_xor_sync(0xffffffffu, s,  off);
        ss += __shfl_xor_sync(0xffffffffu, ss, off);
    }
    __shared__ float sbuf[8], ssbuf[8], red[2];
    int warp = tid >> 5, lane = tid & 31;
    if (lane == 0) { sbuf[warp] = s; ssbuf[warp] = ss; }
    __syncthreads();
    if (tid < 32) {
        float a = (tid < 8) ? sbuf[tid]  : 0.f;
        float c = (tid < 8) ? ssbuf[tid] : 0.f;
        #pragma unroll
        for (int off = 4; off > 0; off >>= 1) {
            a += __shfl_xor_sync(0xffffffffu, a, off);
            c += __shfl_xor_sync(0xffffffffu, c, off);
        }
        if (tid == 0) { red[0] = a; red[1] = c; }
    }
    __syncthreads();
    float mu   = red[0] * (1.0f / EMB);
    float var  = red[1] * (1.0f / EMB) - mu * mu;
    float rstd = rsqrtf(var + 1e-5f);
    float4 gg = ((const float4*)g)[tid];
    float4 bb = ((const float4*)b)[tid];
    float4 o;
    o.x = tf32_rna((v.x - mu) * rstd * gg.x + bb.x);
    o.y = tf32_rna((v.y - mu) * rstd * gg.y + bb.y);
    o.z = tf32_rna((v.z - mu) * rstd * gg.z + bb.z);
    o.w = tf32_rna((v.w - mu) * rstd * gg.w + bb.w);
    ((float4*)(out + (size_t)row * EMB))[tid] = o;
}

// ---------------- TF32 tensor-core GEMM, 3-stage cp.async pipeline ----------
#define APITCH 36
#define BPITCH 136
#define AS_ELEMS (128 * APITCH)
#define BS_ELEMS (32  * BPITCH)
#define NSTAGE 3
#define GEMM_SMEM ((NSTAGE * AS_ELEMS + NSTAGE * BS_ELEMS) * 4)

#define GEMM_ISSUE(k0, buf) do {                                               \
    _Pragma("unroll")                                                          \
    for (int l = 0; l < 4; l++) {                                              \
        int idx = tid + l * 256;                                               \
        int row = idx >> 3, kc = (idx & 7) << 2;                               \
        const float* src = A + (size_t)(m0 + row) * K + (k0) + kc;             \
        unsigned dst = as_base + (unsigned)(((buf) * AS_ELEMS + row * APITCH + kc) * 4); \
        CP_ASYNC16(dst, src);                                                  \
    }                                                                          \
    _Pragma("unroll")                                                          \
    for (int l = 0; l < 4; l++) {                                              \
        int idx = tid + l * 256;                                               \
        int kr = idx >> 5, nc = (idx & 31) << 2;                               \
        const float* src = W + (size_t)((k0) + kr) * N + n0 + nc;              \
        unsigned dst = bs_base + (unsigned)(((buf) * BS_ELEMS + kr * BPITCH + nc) * 4); \
        CP_ASYNC16(dst, src);                                                  \
    }                                                                          \
    CP_COMMIT();                                                               \
} while (0)

template<bool BIAS, bool GELU, bool RES, bool ROUND>
__global__ void __launch_bounds__(256, 2) gemm_tf32_kernel(
    const float* __restrict__ A, const float* __restrict__ W,
    const float* __restrict__ bias, const float* __restrict__ res,
    float* __restrict__ C, int M, int N, int K)
{
    extern __shared__ float sm[];
    float* As = sm;                            // [NSTAGE][128][APITCH]
    float* Bs = sm + NSTAGE * AS_ELEMS;        // [NSTAGE][32][BPITCH]

    const int tid  = threadIdx.x;
    const int lane = tid & 31;
    const int warp = tid >> 5;
    const int wm   = warp & 3;
    const int wn   = warp >> 2;
    const int lm   = lane >> 2;
    const int lk   = lane & 3;
    const int m0 = blockIdx.y * 128, n0 = blockIdx.x * 128;

    unsigned as_base = (unsigned)__cvta_generic_to_shared(As);
    unsigned bs_base = (unsigned)__cvta_generic_to_shared(Bs);

    float acc[2][8][4];
    #pragma unroll
    for (int i = 0; i < 2; i++)
        #pragma unroll
        for (int j = 0; j < 8; j++)
            #pragma unroll
            for (int q = 0; q < 4; q++) acc[i][j][q] = 0.f;

    const int T = K / 32;

    // prologue: stages 0, 1
    GEMM_ISSUE(0, 0);
    GEMM_ISSUE(32, 1);

    int rd = 0;          // buffer being computed
    int wr = 2;          // buffer to fill next
    for (int it = 0; it < T; it++) {
        if (it + 1 < T) CP_WAIT1(); else CP_WAIT0();
        __syncthreads();            // stage `it` visible; all warps done with it-1
        if (it + 2 < T) {
            GEMM_ISSUE((it + 2) * 32, wr);
            wr = (wr == 2) ? 0 : wr + 1;
        }

        const float* Asb = As + rd * AS_ELEMS;
        const float* Bsb = Bs + rd * BS_ELEMS;
        rd = (rd == 2) ? 0 : rd + 1;

        #pragma unroll
        for (int kk = 0; kk < 4; kk++) {
            const int kb = kk * 8;
            unsigned b[8][2], a[2][4];
            #pragma unroll
            for (int jn = 0; jn < 8; jn++) {
                int col = wn * 64 + jn * 8 + lm;
                b[jn][0] = __float_as_uint(Bsb[(kb + lk) * BPITCH + col]);
                b[jn][1] = __float_as_uint(Bsb[(kb + 4 + lk) * BPITCH + col]);
            }
            #pragma unroll
            for (int im = 0; im < 2; im++) {
                int row = wm * 32 + im * 16 + lm;
                a[im][0] = __float_as_uint(Asb[row       * APITCH + kb + lk]);
                a[im][1] = __float_as_uint(Asb[(row + 8) * APITCH + kb + lk]);
                a[im][2] = __float_as_uint(Asb[row       * APITCH + kb + 4 + lk]);
                a[im][3] = __float_as_uint(Asb[(row + 8) * APITCH + kb + 4 + lk]);
            }
            #pragma unroll
            for (int im = 0; im < 2; im++)
                #pragma unroll
                for (int jn = 0; jn < 8; jn++)
                    MMA_TF32(acc[im][jn][0], acc[im][jn][1], acc[im][jn][2], acc[im][jn][3],
                             a[im][0], a[im][1], a[im][2], a[im][3],
                             b[jn][0], b[jn][1]);
        }
        __syncthreads();            // protect buffer reuse by next issue
    }

    #pragma unroll
    for (int im = 0; im < 2; im++) {
        int r0 = m0 + wm * 32 + im * 16 + lm;
        #pragma unroll
        for (int jn = 0; jn < 8; jn++) {
            int c = n0 + wn * 64 + jn * 8 + lk * 2;
            float v[4] = { acc[im][jn][0], acc[im][jn][1],
                           acc[im][jn][2], acc[im][jn][3] };
            if (BIAS) {
                float2 bq = *(const float2*)(bias + c);
                v[0] += bq.x; v[1] += bq.y; v[2] += bq.x; v[3] += bq.y;
            }
            if (GELU) {
                #pragma unroll
                for (int q = 0; q < 4; q++)
                    v[q] = 0.5f * v[q] * (1.0f + erff(v[q] * 0.70710678118654752f));
            }
            if (RES) {
                float2 rlo = *(const float2*)(res + (size_t)r0 * N + c);
                float2 rhi = *(const float2*)(res + (size_t)(r0 + 8) * N + c);
                v[0] += rlo.x; v[1] += rlo.y; v[2] += rhi.x; v[3] += rhi.y;
            }
            if (ROUND) {
                #pragma unroll
                for (int q = 0; q < 4; q++) v[q] = tf32_rna(v[q]);
            }
            float2 lo; lo.x = v[0]; lo.y = v[1];
            float2 hi; hi.x = v[2]; hi.y = v[3];
            *(float2*)(C + (size_t)r0 * N + c)       = lo;
            *(float2*)(C + (size_t)(r0 + 8) * N + c) = hi;
        }
    }
}

// ---------------- Flash attention, tf32 mma + cp.async double-buffered KV ---
// Inputs are pre-rounded tf32 (QKV GEMM epilogue). QKV fused layout:
// row stride 3072; Q at h*64, K at 1024+h*64, V at 2048+h*64.
#define QP 68
#define KP 68
#define VP 72
#define PP 68
#define FLASH_SMEM ((64 * (QP + 2 * KP + 2 * VP + PP)) * 4)

#define FLASH_ISSUE(kvbase, kbuf, vbuf) do {                                   \
    _Pragma("unroll")                                                          \
    for (int l = 0; l < 8; l++) {                                              \
        int idx = tid + l * 128;                                               \
        int c = idx >> 4, d4 = (idx & 15) << 2;                                \
        const float* ksrc = QKV + base_k + (size_t)((kvbase) + c) * QKVN + d4; \
        CP_ASYNC16(ks_base + (unsigned)(((kbuf) * 64 * KP + c * KP + d4) * 4), ksrc); \
        const float* vsrc = QKV + base_v + (size_t)((kvbase) + c) * QKVN + d4; \
        CP_ASYNC16(vs_base + (unsigned)(((vbuf) * 64 * VP + c * VP + d4) * 4), vsrc); \
    }                                                                          \
    CP_COMMIT();                                                               \
} while (0)

__global__ void __launch_bounds__(128) flash_tc_kernel(
    const float* __restrict__ QKV, float* __restrict__ O)
{
    extern __shared__ float smfa[];
    float* Qs = smfa;                  // [64][QP]
    float* Ks = Qs + 64 * QP;          // [2][64][KP]
    float* Vs = Ks + 2 * 64 * KP;      // [2][64][VP]
    float* Ps = Vs + 2 * 64 * VP;      // [64][PP]

    const int tid  = threadIdx.x;
    const int lane = tid & 31;
    const int warp = tid >> 5;
    const int g    = lane >> 2;
    const int t4   = lane & 3;

    const int bh = blockIdx.y;
    const int b = bh >> 4, h = bh & 15;
    const int qb = blockIdx.x;
    const int qbase = qb * 64;
    const size_t base_q = ((size_t)b * 2048) * QKVN + h * 64;
    const size_t base_k = base_q + EMB;
    const size_t base_v = base_q + 2 * EMB;
    const size_t base_o = ((size_t)b * 2048) * EMB + h * 64;

    unsigned ks_base = (unsigned)__cvta_generic_to_shared(Ks);
    unsigned vs_base = (unsigned)__cvta_generic_to_shared(Vs);

    // load Q tile (already tf32-rounded)
    #pragma unroll
    for (int l = 0; l < 8; l++) {
        int idx = tid + l * 128;
        int r = idx >> 4, d4 = (idx & 15) << 2;
        float4 v = *(const float4*)(QKV + base_q + (size_t)(qbase + r) * QKVN + d4);
        *(float4*)&Qs[r * QP + d4] = v;
    }

    // prologue: KV tile 0
    FLASH_ISSUE(0, 0, 0);

    float m0 = -1e30f, m1 = -1e30f, l0 = 0.f, l1 = 0.f;
    float acc[8][4];
    #pragma unroll
    for (int n = 0; n < 8; n++)
        #pragma unroll
        for (int q = 0; q < 4; q++) acc[n][q] = 0.f;

    const int row0l = warp * 16 + g;
    const int grow0 = qbase + row0l;
    const int grow1 = grow0 + 8;
    const float scale = 0.03125f;      // 1/sqrt(1024)

    for (int t = 0; t <= qb; t++) {
        const int kvbase = t * 64;
        if (t < qb) {
            FLASH_ISSUE(kvbase + 64, (t + 1) & 1, (t + 1) & 1);
            CP_WAIT1();
        } else {
            CP_WAIT0();
        }
        __syncthreads();               // stage t visible; Qs visible (t=0)

        const float* Ksb = Ks + (t & 1) * 64 * KP;
        const float* Vsb = Vs + (t & 1) * 64 * VP;

        // ---- S = Q @ K^T ----
        float s[8][4];
        #pragma unroll
        for (int n = 0; n < 8; n++)
            #pragma unroll
            for (int q = 0; q < 4; q++) s[n][q] = 0.f;

        #pragma unroll
        for (int ks = 0; ks < 8; ks++) {
            const int kb = ks * 8;
            unsigned a0 = __float_as_uint(Qs[(row0l    ) * QP + kb + t4]);
            unsigned a1 = __float_as_uint(Qs[(row0l + 8) * QP + kb + t4]);
            unsigned a2 = __float_as_uint(Qs[(row0l    ) * QP + kb + 4 + t4]);
            unsigned a3 = __float_as_uint(Qs[(row0l + 8) * QP + kb + 4 + t4]);
            #pragma unroll
            for (int n = 0; n < 8; n++) {
                unsigned b0 = __float_as_uint(Ksb[(n * 8 + g) * KP + kb + t4]);
                unsigned b1 = __float_as_uint(Ksb[(n * 8 + g) * KP + kb + 4 + t4]);
                MMA_TF32(s[n][0], s[n][1], s[n][2], s[n][3], a0, a1, a2, a3, b0, b1);
            }
        }

        // ---- scale + causal mask ----
        const bool diag = (t == qb);
        #pragma unroll
        for (int n = 0; n < 8; n++) {
            int c0 = kvbase + n * 8 + 2 * t4;
            s[n][0] *= scale; s[n][1] *= scale;
            s[n][2] *= scale; s[n][3] *= scale;
            if (diag) {
                if (c0     > grow0) s[n][0] = -1e30f;
                if (c0 + 1 > grow0) s[n][1] = -1e30f;
                if (c0     > grow1) s[n][2] = -1e30f;
                if (c0 + 1 > grow1) s[n][3] = -1e30f;
            }
        }

        // ---- online softmax ----
        float mx0 = -1e30f, mx1 = -1e30f;
        #pragma unroll
        for (int n = 0; n < 8; n++) {
            mx0 = fmaxf(mx0, fmaxf(s[n][0], s[n][1]));
            mx1 = fmaxf(mx1, fmaxf(s[n][2], s[n][3]));
        }
        mx0 = fmaxf(mx0, __shfl_xor_sync(0xffffffffu, mx0, 1));
        mx0 = fmaxf(mx0, __shfl_xor_sync(0xffffffffu, mx0, 2));
        mx1 = fmaxf(mx1, __shfl_xor_sync(0xffffffffu, mx1, 1));
        mx1 = fmaxf(mx1, __shfl_xor_sync(0xffffffffu, mx1, 2));

        float mn0 = fmaxf(m0, mx0), mn1 = fmaxf(m1, mx1);
        float al0 = __expf(m0 - mn0), al1 = __expf(m1 - mn1);
        m0 = mn0; m1 = mn1;

        float rs0 = 0.f, rs1 = 0.f;
        #pragma unroll
        for (int n = 0; n < 8; n++) {
            s[n][0] = __expf(s[n][0] - mn0);
            s[n][1] = __expf(s[n][1] - mn0);
            s[n][2] = __expf(s[n][2] - mn1);
            s[n][3] = __expf(s[n][3] - mn1);
            rs0 += s[n][0] + s[n][1];
            rs1 += s[n][2] + s[n][3];
        }
        rs0 += __shfl_xor_sync(0xffffffffu, rs0, 1);
        rs0 += __shfl_xor_sync(0xffffffffu, rs0, 2);
        rs1 += __shfl_xor_sync(0xffffffffu, rs1, 1);
        rs1 += __shfl_xor_sync(0xffffffffu, rs1, 2);
        l0 = l0 * al0 + rs0;
        l1 = l1 * al1 + rs1;

        #pragma unroll
        for (int n = 0; n < 8; n++) {
            acc[n][0] *= al0; acc[n][1] *= al0;
            acc[n][2] *= al1; acc[n][3] *= al1;
            float2 plo; plo.x = tf32_rna(s[n][0]); plo.y = tf32_rna(s[n][1]);
            float2 phi; phi.x = tf32_rna(s[n][2]); phi.y = tf32_rna(s[n][3]);
            *(float2*)&Ps[(row0l    ) * PP + n * 8 + 2 * t4] = plo;
            *(float2*)&Ps[(row0l + 8) * PP + n * 8 + 2 * t4] = phi;
        }
        __syncwarp();

        // ---- acc += P @ V ----
        #pragma unroll
        for (int ks = 0; ks < 8; ks++) {
            const int kb = ks * 8;
            unsigned a0 = __float_as_uint(Ps[(row0l    ) * PP + kb + t4]);
            unsigned a1 = __float_as_uint(Ps[(row0l + 8) * PP + kb + t4]);
            unsigned a2 = __float_as_uint(Ps[(row0l    ) * PP + kb + 4 + t4]);
            unsigned a3 = __float_as_uint(Ps[(row0l + 8) * PP + kb + 4 + t4]);
            #pragma unroll
            for (int n = 0; n < 8; n++) {
                unsigned b0 = __float_as_uint(Vsb[(kb + t4    ) * VP + n * 8 + g]);
                unsigned b1 = __float_as_uint(Vsb[(kb + 4 + t4) * VP + n * 8 + g]);
                MMA_TF32(acc[n][0], acc[n][1], acc[n][2], acc[n][3], a0, a1, a2, a3, b0, b1);
            }
        }
        __syncthreads();               // buffer reuse guard for next issue
    }

    // ---- write O = acc / l (tf32-rounded: feeds Wo GEMM) ----
    float inv0 = 1.0f / l0, inv1 = 1.0f / l1;
    #pragma unroll
    for (int n = 0; n < 8; n++) {
        int c = n * 8 + 2 * t4;
        float2 lo; lo.x = tf32_rna(acc[n][0] * inv0); lo.y = tf32_rna(acc[n][1] * inv0);
        float2 hi; hi.x = tf32_rna(acc[n][2] * inv1); hi.y = tf32_rna(acc[n][3] * inv1);
        *(float2*)(O + base_o + (size_t)grow0 * EMB + c) = lo;
        *(float2*)(O + base_o + (size_t)grow1 * EMB + c) = hi;
    }
}

// ---------------- launch ----------------------------------------------------
extern "C" void kernel_launch(void* const* d_in, const int* in_sizes, int n_in,
                              void* d_out, int out_size)
{
    const float* x   = (const float*)d_in[0];
    const float* Wq  = (const float*)d_in[1];
    const float* bq  = (const float*)d_in[2];
    const float* Wk  = (const float*)d_in[3];
    const float* bk  = (const float*)d_in[4];
    const float* Wv  = (const float*)d_in[5];
    const float* bv  = (const float*)d_in[6];
    const float* Wo  = (const float*)d_in[7];
    const float* W1  = (const float*)d_in[8];
    const float* b1  = (const float*)d_in[9];
    const float* W2  = (const float*)d_in[10];
    const float* b2  = (const float*)d_in[11];
    const float* g1  = (const float*)d_in[12];
    const float* be1 = (const float*)d_in[13];
    const float* g2  = (const float*)d_in[14];
    const float* be2 = (const float*)d_in[15];
    float* out = (float*)d_out;

    float *ln1, *qkvb, *zb, *hb, *ln2b, *ffb;
    float *wqkvr, *bqkvr, *wor, *w1r, *w2r;
    cudaGetSymbolAddress((void**)&ln1,   g_ln1);
    cudaGetSymbolAddress((void**)&qkvb,  g_qkv);
    cudaGetSymbolAddress((void**)&zb,    g_z);
    cudaGetSymbolAddress((void**)&hb,    g_h);
    cudaGetSymbolAddress((void**)&ln2b,  g_ln2);
    cudaGetSymbolAddress((void**)&ffb,   g_ff);
    cudaGetSymbolAddress((void**)&wqkvr, g_wqkv);
    cudaGetSymbolAddress((void**)&bqkvr, g_bqkv);
    cudaGetSymbolAddress((void**)&wor,   g_wo);
    cudaGetSymbolAddress((void**)&w1r,   g_w1);
    cudaGetSymbolAddress((void**)&w2r,   g_w2);

    cudaFuncSetAttribute(gemm_tf32_kernel<true,  false, false, true >,
                         cudaFuncAttributeMaxDynamicSharedMemorySize, GEMM_SMEM);
    cudaFuncSetAttribute(gemm_tf32_kernel<false, false, true,  false>,
                         cudaFuncAttributeMaxDynamicSharedMemorySize, GEMM_SMEM);
    cudaFuncSetAttribute(gemm_tf32_kernel<true,  true,  false, true >,
                         cudaFuncAttributeMaxDynamicSharedMemorySize, GEMM_SMEM);
    cudaFuncSetAttribute(gemm_tf32_kernel<true,  false, true,  false>,
                         cudaFuncAttributeMaxDynamicSharedMemorySize, GEMM_SMEM);
    cudaFuncSetAttribute(flash_tc_kernel,
                         cudaFuncAttributeMaxDynamicSharedMemorySize, FLASH_SMEM);

    // 0) weight prep (pack + tf32 round)
    pack_qkv_w_kernel<<<(EMB * QKVN / 4 + 255) / 256, 256>>>(Wq, Wk, Wv, wqkvr);
    pack_qkv_b_kernel<<<(QKVN + 255) / 256, 256>>>(bq, bk, bv, bqkvr);
    {
        int n4a = EMB * EMB / 4;
        round_copy_kernel<<<(n4a + 255) / 256, 256>>>(Wo, wor, n4a);
        int n4b = EMB * FFD / 4;
        round_copy_kernel<<<(n4b + 255) / 256, 256>>>(W1, w1r, n4b);
        round_copy_kernel<<<(n4b + 255) / 256, 256>>>(W2, w2r, n4b);
    }

    // 1) ln1 = round(LN(x))
    layernorm_kernel<<<NTOK, 256>>>(x, g1, be1, ln1);

    // 2) fused QKV projection, tf32-rounded output
    gemm_tf32_kernel<true, false, false, true><<<dim3(QKVN / 128, NTOK / 128), 256, GEMM_SMEM>>>(
        ln1, wqkvr, bqkvr, nullptr, qkvb, NTOK, QKVN, EMB);

    // 3) causal flash attention (tf32 mma, cp.async KV pipeline)
    flash_tc_kernel<<<dim3(32, 32), 128, FLASH_SMEM>>>(qkvb, zb);

    // 4) h = x + z @ Wo
    gemm_tf32_kernel<false, false, true, false><<<dim3(EMB / 128, NTOK / 128), 256, GEMM_SMEM>>>(
        zb, wor, nullptr, x, hb, NTOK, EMB, EMB);

    // 5) ln2 = round(LN(h))
    layernorm_kernel<<<NTOK, 256>>>(hb, g2, be2, ln2b);

    // 6) ff = round(gelu(ln2 @ W1 + b1))
    gemm_tf32_kernel<true, true, false, true><<<dim3(FFD / 128, NTOK / 128), 256, GEMM_SMEM>>>(
        ln2b, w1r, b1, nullptr, ffb, NTOK, FFD, EMB);

    // 7) out = h + ff @ W2 + b2
    gemm_tf32_kernel<true, false, true, false><<<dim3(EMB / 128, NTOK / 128), 256, GEMM_SMEM>>>(
        ffb, w2r, b2, hb, out, NTOK, EMB, FFD);
}

// round 10
// speedup vs baseline: 5.0883x; 1.3363x over previous
#include <cuda_runtime.h>
#include <cuda_fp16.h>
#include <math.h>

// ---------------- scratch (device globals; no allocation allowed) ----------
#define NTOK 4096            // B*S = 2*2048
#define EMB  1024
#define FFD  4096
#define QKVN 3072

__device__ __half g_ln1h[NTOK * EMB];
__device__ __half g_qkvh[NTOK * QKVN];
__device__ __half g_zh  [NTOK * EMB];
__device__ float  g_h   [NTOK * EMB];
__device__ __half g_ln2h[NTOK * EMB];
__device__ __half g_ffh [NTOK * FFD];
// fp16 TRANSPOSED weights: [N][K] K-major
__device__ __half g_wqkv[QKVN * EMB];
__device__ float  g_bqkv[QKVN];
__device__ __half g_wo  [EMB * EMB];
__device__ __half g_w1t [FFD * EMB];
__device__ __half g_w2t [EMB * FFD];

// ---------------- helpers ---------------------------------------------------
#define CP_ASYNC16(dst_u32, src_ptr) \
    asm volatile("cp.async.cg.shared.global [%0], [%1], 16;" :: "r"(dst_u32), "l"(src_ptr))
#define CP_COMMIT() asm volatile("cp.async.commit_group;")
#define CP_WAIT1()  asm volatile("cp.async.wait_group 1;")
#define CP_WAIT0()  asm volatile("cp.async.wait_group 0;")

#define MMA_F16(d0,d1,d2,d3, a0,a1,a2,a3, b0,b1) \
    asm volatile( \
        "mma.sync.aligned.m16n8k16.row.col.f32.f16.f16.f32 " \
        "{%0,%1,%2,%3}, {%4,%5,%6,%7}, {%8,%9}, {%0,%1,%2,%3};" \
        : "+f"(d0), "+f"(d1), "+f"(d2), "+f"(d3) \
        : "r"(a0), "r"(a1), "r"(a2), "r"(a3), "r"(b0), "r"(b1))

// ---------------- weight prep: tiled transpose + fp16 round -----------------
// in: fp32 [K][N] row-major -> out: fp16 [N][K] row-major (K-major B operand)
__global__ void __launch_bounds__(256) transpose_h_kernel(
    const float* __restrict__ in, __half* __restrict__ out, int K, int N)
{
    __shared__ float tile[32][33];
    int n0 = blockIdx.x * 32, k0 = blockIdx.y * 32;
    int tx = threadIdx.x & 31, ty = threadIdx.x >> 5;   // ty 0..7
    #pragma unroll
    for (int i = 0; i < 32; i += 8)
        tile[ty + i][tx] = in[(size_t)(k0 + ty + i) * N + n0 + tx];
    __syncthreads();
    #pragma unroll
    for (int i = 0; i < 32; i += 8)
        out[(size_t)(n0 + ty + i) * K + k0 + tx] = __float2half_rn(tile[tx][ty + i]);
}

__global__ void __launch_bounds__(256) pack_qkv_b_kernel(
    const float* __restrict__ bq, const float* __restrict__ bk,
    const float* __restrict__ bv, float* __restrict__ out)
{
    int i = blockIdx.x * blockDim.x + threadIdx.x;
    if (i >= QKVN) return;
    out[i] = (i < EMB) ? bq[i] : (i < 2 * EMB) ? bk[i - EMB] : bv[i - 2 * EMB];
}

// ---------------- LayerNorm (fp16 output: feeds GEMMs) ----------------------
__global__ void __launch_bounds__(256) layernorm_kernel(
    const float* __restrict__ x, const float* __restrict__ g,
    const float* __restrict__ b, __half* __restrict__ out)
{
    int row = blockIdx.x;
    int tid = threadIdx.x;
    const float4* xr = (const float4*)(x + (size_t)row * EMB);
    float4 v = xr[tid];
    float s  = v.x + v.y + v.z + v.w;
    float ss = v.x*v.x + v.y*v.y + v.z*v.z + v.w*v.w;
    #pragma unroll
    for (int off = 16; off > 0; off >>= 1) {
        s  += __shfl_xor_sync(0xffffffffu, s,  off);
        ss += __shfl_xor_sync(0xffffffffu, ss, off);
    }
    __shared__ float sbuf[8], ssbuf[8], red[2];
    int warp = tid >> 5, lane = tid & 31;
    if (lane == 0) { sbuf[warp] = s; ssbuf[warp] = ss; }
    __syncthreads();
    if (tid < 32) {
        float a = (tid < 8) ? sbuf[tid]  : 0.f;
        float c = (tid < 8) ? ssbuf[tid] : 0.f;
        #pragma unroll
        for (int off = 4; off > 0; off >>= 1) {
            a += __shfl_xor_sync(0xffffffffu, a, off);
            c += __shfl_xor_sync(0xffffffffu, c, off);
        }
        if (tid == 0) { red[0] = a; red[1] = c; }
    }
    __syncthreads();
    float mu   = red[0] * (1.0f / EMB);
    float var  = red[1] * (1.0f / EMB) - mu * mu;
    float rstd = rsqrtf(var + 1e-5f);
    float4 gg = ((const float4*)g)[tid];
    float4 bb = ((const float4*)b)[tid];
    __half2 p0 = __floats2half2_rn((v.x - mu) * rstd * gg.x + bb.x,
                                   (v.y - mu) * rstd * gg.y + bb.y);
    __half2 p1 = __floats2half2_rn((v.z - mu) * rstd * gg.z + bb.z,
                                   (v.w - mu) * rstd * gg.w + bb.w);
    uint2 pk;
    pk.x = *(unsigned*)&p0; pk.y = *(unsigned*)&p1;
    ((uint2*)(out + (size_t)row * EMB))[tid] = pk;
}

// ---------------- FP16 tensor-core GEMM, 3-stage cp.async pipeline ----------
// C[M,N] = A[M,K] @ Wt[N,K]^T (+bias)(gelu)(+res). A, Wt are __half.
// 128x128 tile, BK=32 halves, 256 threads, 8 warps 4(M)x2(N),
// warp tile 32x64 -> per k16-step 2x8 m16n8k16 mmas. Pitch 40 halves (80B:
// bank = r*20+t4 mod 32, all 32 distinct).
#define APH 40
#define HALF_STG (128 * APH)                 // halves per matrix per stage
#define STG_BYTES (2 * HALF_STG * 2)         // A + B, bytes
#define NSTAGE 3
#define GEMM_SMEM (NSTAGE * STG_BYTES)

#define GEMM_ISSUE(k0, buf) do {                                                \
    _Pragma("unroll")                                                           \
    for (int l = 0; l < 2; l++) {                                               \
        int idx = tid + l * 256;                                                \
        int r = idx >> 2, c = idx & 3;                                          \
        const __half* src = A + (size_t)(m0 + r) * K + (k0) + c * 8;            \
        CP_ASYNC16(as_base + (unsigned)((buf) * STG_BYTES + r * 80 + c * 16), src); \
    }                                                                           \
    _Pragma("unroll")                                                           \
    for (int l = 0; l < 2; l++) {                                               \
        int idx = tid + l * 256;                                                \
        int r = idx >> 2, c = idx & 3;                                          \
        const __half* src = Wt + (size_t)(n0 + r) * K + (k0) + c * 8;           \
        CP_ASYNC16(bs_base + (unsigned)((buf) * STG_BYTES + r * 80 + c * 16), src); \
    }                                                                           \
    CP_COMMIT();                                                                \
} while (0)

template<bool BIAS, bool GELU, bool RES, bool OUTH>
__global__ void __launch_bounds__(256, 2) gemm_f16_kernel(
    const __half* __restrict__ A, const __half* __restrict__ Wt,
    const float* __restrict__ bias, const float* __restrict__ res,
    void* __restrict__ Cv, int M, int N, int K)
{
    extern __shared__ __half smh[];
    __half* As = smh;                                // [NSTAGE][128][APH]
    __half* Bs = smh + HALF_STG;                     // interleaved per stage

    const int tid  = threadIdx.x;
    const int lane = tid & 31;
    const int warp = tid >> 5;
    const int wm   = warp & 3;
    const int wn   = warp >> 2;
    const int g    = lane >> 2;
    const int t4   = lane & 3;
    const int m0 = blockIdx.y * 128, n0 = blockIdx.x * 128;

    unsigned as_base = (unsigned)__cvta_generic_to_shared(As);
    unsigned bs_base = (unsigned)__cvta_generic_to_shared(Bs);

    float acc[2][8][4];
    #pragma unroll
    for (int i = 0; i < 2; i++)
        #pragma unroll
        for (int j = 0; j < 8; j++)
            #pragma unroll
            for (int q = 0; q < 4; q++) acc[i][j][q] = 0.f;

    const int T = K / 32;
    GEMM_ISSUE(0, 0);
    GEMM_ISSUE(32, 1);

    int rd = 0, wr = 2;
    for (int it = 0; it < T; it++) {
        if (it + 1 < T) CP_WAIT1(); else CP_WAIT0();
        __syncthreads();
        if (it + 2 < T) {
            GEMM_ISSUE((it + 2) * 32, wr);
            wr = (wr == 2) ? 0 : wr + 1;
        }

        const __half* Asb = As + rd * (STG_BYTES / 2);
        const __half* Bsb = Bs + rd * (STG_BYTES / 2);
        rd = (rd == 2) ? 0 : rd + 1;

        #pragma unroll
        for (int ks = 0; ks < 2; ks++) {
            const int kb = ks * 16;
            unsigned b[8][2], a[2][4];
            #pragma unroll
            for (int jn = 0; jn < 8; jn++) {
                int n = wn * 64 + jn * 8 + g;
                b[jn][0] = *(const unsigned*)&Bsb[n * APH + kb + 2 * t4];
                b[jn][1] = *(const unsigned*)&Bsb[n * APH + kb + 8 + 2 * t4];
            }
            #pragma unroll
            for (int im = 0; im < 2; im++) {
                int row = wm * 32 + im * 16 + g;
                a[im][0] = *(const unsigned*)&Asb[row       * APH + kb + 2 * t4];
                a[im][1] = *(const unsigned*)&Asb[(row + 8) * APH + kb + 2 * t4];
                a[im][2] = *(const unsigned*)&Asb[row       * APH + kb + 8 + 2 * t4];
                a[im][3] = *(const unsigned*)&Asb[(row + 8) * APH + kb + 8 + 2 * t4];
            }
            #pragma unroll
            for (int im = 0; im < 2; im++)
                #pragma unroll
                for (int jn = 0; jn < 8; jn++)
                    MMA_F16(acc[im][jn][0], acc[im][jn][1], acc[im][jn][2], acc[im][jn][3],
                            a[im][0], a[im][1], a[im][2], a[im][3],
                            b[jn][0], b[jn][1]);
        }
        __syncthreads();
    }

    // ---- epilogue ----
    #pragma unroll
    for (int im = 0; im < 2; im++) {
        int r0 = m0 + wm * 32 + im * 16 + g;     // rows r0 and r0+8
        #pragma unroll
        for (int jn = 0; jn < 8; jn++) {
            int c = n0 + wn * 64 + jn * 8 + t4 * 2;
            float v[4] = { acc[im][jn][0], acc[im][jn][1],
                           acc[im][jn][2], acc[im][jn][3] };
            if (BIAS) {
                float2 bq = *(const float2*)(bias + c);
                v[0] += bq.x; v[1] += bq.y; v[2] += bq.x; v[3] += bq.y;
            }
            if (GELU) {
                #pragma unroll
                for (int q = 0; q < 4; q++)
                    v[q] = 0.5f * v[q] * (1.0f + erff(v[q] * 0.70710678118654752f));
            }
            if (RES) {
                float2 rlo = *(const float2*)(res + (size_t)r0 * N + c);
                float2 rhi = *(const float2*)(res + (size_t)(r0 + 8) * N + c);
                v[0] += rlo.x; v[1] += rlo.y; v[2] += rhi.x; v[3] += rhi.y;
            }
            if (OUTH) {
                __half* C = (__half*)Cv;
                *(__half2*)(C + (size_t)r0 * N + c)       = __floats2half2_rn(v[0], v[1]);
                *(__half2*)(C + (size_t)(r0 + 8) * N + c) = __floats2half2_rn(v[2], v[3]);
            } else {
                float* C = (float*)Cv;
                float2 lo; lo.x = v[0]; lo.y = v[1];
                float2 hi; hi.x = v[2]; hi.y = v[3];
                *(float2*)(C + (size_t)r0 * N + c)       = lo;
                *(float2*)(C + (size_t)(r0 + 8) * N + c) = hi;
            }
        }
    }
}

// ---------------- Flash attention, fp16 mma ---------------------------------
// BQ=BKV=64, D=64. 128 threads / 4 warps; warp = 16 q-rows. fp32 softmax.
// Q/K/P/Vt pitch 72 halves (144B): fragment u32 loads hit 32 distinct banks.
// K double-buffered via cp.async; V register-prefetched + transposed (Vt[d][kv]).
#define FP 72
#define FLASH_SMEM ((64 * FP) * 5 * 2)   // Q + 2*K + Vt + P, halves*2 bytes

#define FLASH_K_ISSUE(kvbase, buf) do {                                         \
    _Pragma("unroll")                                                           \
    for (int l = 0; l < 4; l++) {                                               \
        int idx = tid + l * 128;                                                \
        int r = idx >> 3, c = idx & 7;                                          \
        const __half* src = QKV + base_k + (size_t)((kvbase) + r) * QKVN + c * 8; \
        CP_ASYNC16(ks_base + (unsigned)((buf) * 64 * 144 + r * 144 + c * 16), src); \
    }                                                                           \
    CP_COMMIT();                                                                \
} while (0)

__global__ void __launch_bounds__(128) flash_f16_kernel(
    const __half* __restrict__ QKV, __half* __restrict__ O)
{
    extern __shared__ __half smf[];
    __half* Qs  = smf;                    // [64][FP]
    __half* Ks  = Qs  + 64 * FP;          // [2][64][FP]
    __half* Vts = Ks  + 2 * 64 * FP;      // [64][FP]  V^T: [d][kv]
    __half* Ps  = Vts + 64 * FP;          // [64][FP]

    const int tid  = threadIdx.x;
    const int lane = tid & 31;
    const int warp = tid >> 5;
    const int g    = lane >> 2;
    const int t4   = lane & 3;

    const int bh = blockIdx.y;
    const int b = bh >> 4, h = bh & 15;
    const int qb = blockIdx.x;
    const int qbase = qb * 64;
    const size_t base_q = ((size_t)b * 2048) * QKVN + h * 64;
    const size_t base_k = base_q + EMB;
    const size_t base_v = base_q + 2 * EMB;
    const size_t base_o = ((size_t)b * 2048) * EMB + h * 64;

    unsigned qs_base = (unsigned)__cvta_generic_to_shared(Qs);
    unsigned ks_base = (unsigned)__cvta_generic_to_shared(Ks);

    // prologue: Q + K0 via cp.async (one group)
    #pragma unroll
    for (int l = 0; l < 4; l++) {
        int idx = tid + l * 128;
        int r = idx >> 3, c = idx & 7;
        const __half* src = QKV + base_q + (size_t)(qbase + r) * QKVN + c * 8;
        CP_ASYNC16(qs_base + (unsigned)(r * 144 + c * 16), src);
    }
    {
        #pragma unroll
        for (int l = 0; l < 4; l++) {
            int idx = tid + l * 128;
            int r = idx >> 3, c = idx & 7;
            const __half* src = QKV + base_k + (size_t)(0 + r) * QKVN + c * 8;
            CP_ASYNC16(ks_base + (unsigned)(r * 144 + c * 16), src);
        }
        CP_COMMIT();
    }

    // V: thread owns kv row tid>>1, d-range (tid&1)*32 .. +31
    const int vrow = tid >> 1;
    const int vd0  = (tid & 1) * 32;
    __half2 vreg[16];
    #pragma unroll
    for (int j = 0; j < 16; j++)
        vreg[j] = *(const __half2*)(QKV + base_v + (size_t)vrow * QKVN + vd0 + 2 * j);
    #pragma unroll
    for (int j = 0; j < 16; j++) {
        Vts[(vd0 + 2 * j    ) * FP + vrow] = __low2half(vreg[j]);
        Vts[(vd0 + 2 * j + 1) * FP + vrow] = __high2half(vreg[j]);
    }

    float m0 = -1e30f, m1 = -1e30f, l0 = 0.f, l1 = 0.f;
    float acc[8][4];
    #pragma unroll
    for (int n = 0; n < 8; n++)
        #pragma unroll
        for (int q = 0; q < 4; q++) acc[n][q] = 0.f;

    const int row0l = warp * 16 + g;
    const int grow0 = qbase + row0l;
    const int grow1 = grow0 + 8;
    const float scale = 0.03125f;      // 1/sqrt(1024)

    for (int t = 0; t <= qb; t++) {
        const int kvbase = t * 64;
        if (t < qb) {
            FLASH_K_ISSUE(kvbase + 64, (t + 1) & 1);
            // prefetch V(t+1) into regs (latency hidden by QK+softmax)
            #pragma unroll
            for (int j = 0; j < 16; j++)
                vreg[j] = *(const __half2*)(QKV + base_v +
                    (size_t)(kvbase + 64 + vrow) * QKVN + vd0 + 2 * j);
            CP_WAIT1();
        } else {
            CP_WAIT0();
        }
        __syncthreads();   // K[t] + Vt(t) stores + (t=0) Qs visible

        const __half* Ksb = Ks + (t & 1) * 64 * FP;

        // ---- S = Q @ K^T ----
        float s[8][4];
        #pragma unroll
        for (int n = 0; n < 8; n++)
            #pragma unroll
            for (int q = 0; q < 4; q++) s[n][q] = 0.f;

        #pragma unroll
        for (int ks = 0; ks < 4; ks++) {
            const int kb = ks * 16;
            unsigned a0 = *(const unsigned*)&Qs[(row0l    ) * FP + kb + 2 * t4];
            unsigned a1 = *(const unsigned*)&Qs[(row0l + 8) * FP + kb + 2 * t4];
            unsigned a2 = *(const unsigned*)&Qs[(row0l    ) * FP + kb + 8 + 2 * t4];
            unsigned a3 = *(const unsigned*)&Qs[(row0l + 8) * FP + kb + 8 + 2 * t4];
            #pragma unroll
            for (int n = 0; n < 8; n++) {
                int kr = n * 8 + g;
                unsigned b0 = *(const unsigned*)&Ksb[kr * FP + kb + 2 * t4];
                unsigned b1 = *(const unsigned*)&Ksb[kr * FP + kb + 8 + 2 * t4];
                MMA_F16(s[n][0], s[n][1], s[n][2], s[n][3], a0, a1, a2, a3, b0, b1);
            }
        }

        // ---- scale + causal mask ----
        const bool diag = (t == qb);
        #pragma unroll
        for (int n = 0; n < 8; n++) {
            int c0 = kvbase + n * 8 + 2 * t4;
            s[n][0] *= scale; s[n][1] *= scale;
            s[n][2] *= scale; s[n][3] *= scale;
            if (diag) {
                if (c0     > grow0) s[n][0] = -1e30f;
                if (c0 + 1 > grow0) s[n][1] = -1e30f;
                if (c0     > grow1) s[n][2] = -1e30f;
                if (c0 + 1 > grow1) s[n][3] = -1e30f;
            }
        }

        // ---- online softmax (fp32) ----
        float mx0 = -1e30f, mx1 = -1e30f;
        #pragma unroll
        for (int n = 0; n < 8; n++) {
            mx0 = fmaxf(mx0, fmaxf(s[n][0], s[n][1]));
            mx1 = fmaxf(mx1, fmaxf(s[n][2], s[n][3]));
        }
        mx0 = fmaxf(mx0, __shfl_xor_sync(0xffffffffu, mx0, 1));
        mx0 = fmaxf(mx0, __shfl_xor_sync(0xffffffffu, mx0, 2));
        mx1 = fmaxf(mx1, __shfl_xor_sync(0xffffffffu, mx1, 1));
        mx1 = fmaxf(mx1, __shfl_xor_sync(0xffffffffu, mx1, 2));

        float mn0 = fmaxf(m0, mx0), mn1 = fmaxf(m1, mx1);
        float al0 = __expf(m0 - mn0), al1 = __expf(m1 - mn1);
        m0 = mn0; m1 = mn1;

        float rs0 = 0.f, rs1 = 0.f;
        #pragma unroll
        for (int n = 0; n < 8; n++) {
            s[n][0] = __expf(s[n][0] - mn0);
            s[n][1] = __expf(s[n][1] - mn0);
            s[n][2] = __expf(s[n][2] - mn1);
            s[n][3] = __expf(s[n][3] - mn1);
            rs0 += s[n][0] + s[n][1];
            rs1 += s[n][2] + s[n][3];
        }
        rs0 += __shfl_xor_sync(0xffffffffu, rs0, 1);
        rs0 += __shfl_xor_sync(0xffffffffu, rs0, 2);
        rs1 += __shfl_xor_sync(0xffffffffu, rs1, 1);
        rs1 += __shfl_xor_sync(0xffffffffu, rs1, 2);
        l0 = l0 * al0 + rs0;
        l1 = l1 * al1 + rs1;

        #pragma unroll
        for (int n = 0; n < 8; n++) {
            acc[n][0] *= al0; acc[n][1] *= al0;
            acc[n][2] *= al1; acc[n][3] *= al1;
            *(__half2*)&Ps[(row0l    ) * FP + n * 8 + 2 * t4] =
                __floats2half2_rn(s[n][0], s[n][1]);
            *(__half2*)&Ps[(row0l + 8) * FP + n * 8 + 2 * t4] =
                __floats2half2_rn(s[n][2], s[n][3]);
        }
        __syncwarp();   // each warp reads only its own P rows

        // ---- acc += P @ V  (B = Vt[d][kv]) ----
        #pragma unroll
        for (int ks = 0; ks < 4; ks++) {
            const int kb = ks * 16;
            unsigned a0 = *(const unsigned*)&Ps[(row0l    ) * FP + kb + 2 * t4];
            unsigned a1 = *(const unsigned*)&Ps[(row0l + 8) * FP + kb + 2 * t4];
            unsigned a2 = *(const unsigned*)&Ps[(row0l    ) * FP + kb + 8 + 2 * t4];
            unsigned a3 = *(const unsigned*)&Ps[(row0l + 8) * FP + kb + 8 + 2 * t4];
            #pragma unroll
            for (int n = 0; n < 8; n++) {
                int d = n * 8 + g;
                unsigned b0 = *(const unsigned*)&Vts[d * FP + kb + 2 * t4];
                unsigned b1 = *(const unsigned*)&Vts[d * FP + kb + 8 + 2 * t4];
                MMA_F16(acc[n][0], acc[n][1], acc[n][2], acc[n][3], a0, a1, a2, a3, b0, b1);
            }
        }
        __syncthreads();   // all warps done reading Vts

        if (t < qb) {
            // store V(t+1) transposed into Vts
            #pragma unroll
            for (int j = 0; j < 16; j++) {
                Vts[(vd0 + 2 * j    ) * FP + vrow] = __low2half(vreg[j]);
                Vts[(vd0 + 2 * j + 1) * FP + vrow] = __high2half(vreg[j]);
            }
        }
    }

    // ---- write O = acc / l as fp16 (feeds Wo GEMM) ----
    float inv0 = 1.0f / l0, inv1 = 1.0f / l1;
    #pragma unroll
    for (int n = 0; n < 8; n++) {
        int c = n * 8 + 2 * t4;
        *(__half2*)(O + base_o + (size_t)grow0 * EMB + c) =
            __floats2half2_rn(acc[n][0] * inv0, acc[n][1] * inv0);
        *(__half2*)(O + base_o + (size_t)grow1 * EMB + c) =
            __floats2half2_rn(acc[n][2] * inv1, acc[n][3] * inv1);
    }
}

// ---------------- launch ----------------------------------------------------
extern "C" void kernel_launch(void* const* d_in, const int* in_sizes, int n_in,
                              void* d_out, int out_size)
{
    const float* x   = (const float*)d_in[0];
    const float* Wq  = (const float*)d_in[1];
    const float* bq  = (const float*)d_in[2];
    const float* Wk  = (const float*)d_in[3];
    const float* bk  = (const float*)d_in[4];
    const float* Wv  = (const float*)d_in[5];
    const float* bv  = (const float*)d_in[6];
    const float* Wo  = (const float*)d_in[7];
    const float* W1  = (const float*)d_in[8];
    const float* b1  = (const float*)d_in[9];
    const float* W2  = (const float*)d_in[10];
    const float* b2  = (const float*)d_in[11];
    const float* g1  = (const float*)d_in[12];
    const float* be1 = (const float*)d_in[13];
    const float* g2  = (const float*)d_in[14];
    const float* be2 = (const float*)d_in[15];
    float* out = (float*)d_out;

    __half *ln1h, *qkvh, *zh, *ln2h, *ffh, *wqkv, *wo, *w1t, *w2t;
    float *hb, *bqkv;
    cudaGetSymbolAddress((void**)&ln1h, g_ln1h);
    cudaGetSymbolAddress((void**)&qkvh, g_qkvh);
    cudaGetSymbolAddress((void**)&zh,   g_zh);
    cudaGetSymbolAddress((void**)&hb,   g_h);
    cudaGetSymbolAddress((void**)&ln2h, g_ln2h);
    cudaGetSymbolAddress((void**)&ffh,  g_ffh);
    cudaGetSymbolAddress((void**)&wqkv, g_wqkv);
    cudaGetSymbolAddress((void**)&bqkv, g_bqkv);
    cudaGetSymbolAddress((void**)&wo,   g_wo);
    cudaGetSymbolAddress((void**)&w1t,  g_w1t);
    cudaGetSymbolAddress((void**)&w2t,  g_w2t);

    cudaFuncSetAttribute(gemm_f16_kernel<true,  false, false, true >,
                         cudaFuncAttributeMaxDynamicSharedMemorySize, GEMM_SMEM);
    cudaFuncSetAttribute(gemm_f16_kernel<false, false, true,  false>,
                         cudaFuncAttributeMaxDynamicSharedMemorySize, GEMM_SMEM);
    cudaFuncSetAttribute(gemm_f16_kernel<true,  true,  false, true >,
                         cudaFuncAttributeMaxDynamicSharedMemorySize, GEMM_SMEM);
    cudaFuncSetAttribute(gemm_f16_kernel<true,  false, true,  false>,
                         cudaFuncAttributeMaxDynamicSharedMemorySize, GEMM_SMEM);
    cudaFuncSetAttribute(flash_f16_kernel,
                         cudaFuncAttributeMaxDynamicSharedMemorySize, FLASH_SMEM);

    // 0) weight prep: transpose + fp16 round into [N][K] buffers
    transpose_h_kernel<<<dim3(EMB / 32, EMB / 32), 256>>>(Wq, wqkv,                 EMB, EMB);
    transpose_h_kernel<<<dim3(EMB / 32, EMB / 32), 256>>>(Wk, wqkv + EMB * EMB,     EMB, EMB);
    transpose_h_kernel<<<dim3(EMB / 32, EMB / 32), 256>>>(Wv, wqkv + 2 * EMB * EMB, EMB, EMB);
    transpose_h_kernel<<<dim3(EMB / 32, EMB / 32), 256>>>(Wo, wo,  EMB, EMB);
    transpose_h_kernel<<<dim3(FFD / 32, EMB / 32), 256>>>(W1, w1t, EMB, FFD);
    transpose_h_kernel<<<dim3(EMB / 32, FFD / 32), 256>>>(W2, w2t, FFD, EMB);
    pack_qkv_b_kernel<<<(QKVN + 255) / 256, 256>>>(bq, bk, bv, bqkv);

    // 1) ln1 = fp16(LN(x))
    layernorm_kernel<<<NTOK, 256>>>(x, g1, be1, ln1h);

    // 2) fused QKV projection (fp16 mma), fp16 output
    gemm_f16_kernel<true, false, false, true><<<dim3(QKVN / 128, NTOK / 128), 256, GEMM_SMEM>>>(
        ln1h, wqkv, bqkv, nullptr, qkvh, NTOK, QKVN, EMB);

    // 3) causal flash attention (fp16 mma, fp32 softmax)
    flash_f16_kernel<<<dim3(32, 32), 128, FLASH_SMEM>>>(qkvh, zh);

    // 4) h = x + z @ Wo  (fp32 output)
    gemm_f16_kernel<false, false, true, false><<<dim3(EMB / 128, NTOK / 128), 256, GEMM_SMEM>>>(
        zh, wo, nullptr, x, hb, NTOK, EMB, EMB);

    // 5) ln2 = fp16(LN(h))
    layernorm_kernel<<<NTOK, 256>>>(hb, g2, be2, ln2h);

    // 6) ff = fp16(gelu(ln2 @ W1 + b1))
    gemm_f16_kernel<true, true, false, true><<<dim3(FFD / 128, NTOK / 128), 256, GEMM_SMEM>>>(
        ln2h, w1t, b1, nullptr, ffh, NTOK, FFD, EMB);

    // 7) out = h + ff @ W2 + b2  (fp32 output)
    gemm_f16_kernel<true, false, true, false><<<dim3(EMB / 128, NTOK / 128), 256, GEMM_SMEM>>>(
        ffh, w2t, b2, hb, out, NTOK, EMB, FFD);
}

// round 12
// speedup vs baseline: 6.0012x; 1.1794x over previous
#include <cuda_runtime.h>
#include <cuda_fp16.h>
#include <math.h>

// ---------------- scratch (device globals; no allocation allowed) ----------
#define NTOK 4096            // B*S = 2*2048
#define EMB  1024
#define FFD  4096
#define QKVN 3072

__device__ __half g_ln1h[NTOK * EMB];
__device__ __half g_qkvh[NTOK * QKVN];
__device__ __half g_zh  [NTOK * EMB];
__device__ float  g_h   [NTOK * EMB];
__device__ __half g_ln2h[NTOK * EMB];
__device__ __half g_ffh [NTOK * FFD];
// fp16 TRANSPOSED weights: [N][K] K-major
__device__ __half g_wqkv[QKVN * EMB];
__device__ float  g_bqkv[QKVN];
__device__ __half g_wo  [EMB * EMB];
__device__ __half g_w1t [FFD * EMB];
__device__ __half g_w2t [EMB * FFD];

// ---------------- helpers ---------------------------------------------------
#define CP_ASYNC16(dst_u32, src_ptr) \
    asm volatile("cp.async.cg.shared.global [%0], [%1], 16;" :: "r"(dst_u32), "l"(src_ptr))
#define CP_COMMIT() asm volatile("cp.async.commit_group;")
#define CP_WAIT1()  asm volatile("cp.async.wait_group 1;")
#define CP_WAIT0()  asm volatile("cp.async.wait_group 0;")

#define MMA_F16(d0,d1,d2,d3, a0,a1,a2,a3, b0,b1) \
    asm volatile( \
        "mma.sync.aligned.m16n8k16.row.col.f32.f16.f16.f32 " \
        "{%0,%1,%2,%3}, {%4,%5,%6,%7}, {%8,%9}, {%0,%1,%2,%3};" \
        : "+f"(d0), "+f"(d1), "+f"(d2), "+f"(d3) \
        : "r"(a0), "r"(a1), "r"(a2), "r"(a3), "r"(b0), "r"(b1))

// ---------------- fused weight prep: all 6 transposes in one launch ---------
// fp32 [K][N] row-major -> fp16 [N][K] row-major. 1D grid, 12288 blocks.
__global__ void __launch_bounds__(256) prep_weights_kernel(
    const float* __restrict__ Wq, const float* __restrict__ Wk,
    const float* __restrict__ Wv, const float* __restrict__ Wo,
    const float* __restrict__ W1, const float* __restrict__ W2,
    __half* __restrict__ wqkv, __half* __restrict__ wo,
    __half* __restrict__ w1t, __half* __restrict__ w2t)
{
    int bid = blockIdx.x;
    const float* src; __half* dst; int K, N, ti;
    if (bid < 1024)      { src = Wq; dst = wqkv;               K = EMB; N = EMB; ti = bid; }
    else if (bid < 2048) { src = Wk; dst = wqkv + EMB * EMB;   K = EMB; N = EMB; ti = bid - 1024; }
    else if (bid < 3072) { src = Wv; dst = wqkv + 2*EMB*EMB;   K = EMB; N = EMB; ti = bid - 2048; }
    else if (bid < 4096) { src = Wo; dst = wo;                 K = EMB; N = EMB; ti = bid - 3072; }
    else if (bid < 8192) { src = W1; dst = w1t;                K = EMB; N = FFD; ti = bid - 4096; }
    else                 { src = W2; dst = w2t;                K = FFD; N = EMB; ti = bid - 8192; }
    int nx = N / 32;
    int n0 = (ti % nx) * 32, k0 = (ti / nx) * 32;

    __shared__ float tile[32][33];
    int tx = threadIdx.x & 31, ty = threadIdx.x >> 5;   // ty 0..7
    #pragma unroll
    for (int i = 0; i < 32; i += 8)
        tile[ty + i][tx] = src[(size_t)(k0 + ty + i) * N + n0 + tx];
    __syncthreads();
    #pragma unroll
    for (int i = 0; i < 32; i += 8)
        dst[(size_t)(n0 + ty + i) * K + k0 + tx] = __float2half_rn(tile[tx][ty + i]);
}

__global__ void __launch_bounds__(256) pack_qkv_b_kernel(
    const float* __restrict__ bq, const float* __restrict__ bk,
    const float* __restrict__ bv, float* __restrict__ out)
{
    int i = blockIdx.x * blockDim.x + threadIdx.x;
    if (i >= QKVN) return;
    out[i] = (i < EMB) ? bq[i] : (i < 2 * EMB) ? bk[i - EMB] : bv[i - 2 * EMB];
}

// ---------------- LayerNorm (fp16 output: feeds GEMMs) ----------------------
__global__ void __launch_bounds__(256) layernorm_kernel(
    const float* __restrict__ x, const float* __restrict__ g,
    const float* __restrict__ b, __half* __restrict__ out)
{
    int row = blockIdx.x;
    int tid = threadIdx.x;
    const float4* xr = (const float4*)(x + (size_t)row * EMB);
    float4 v = xr[tid];
    float s  = v.x + v.y + v.z + v.w;
    float ss = v.x*v.x + v.y*v.y + v.z*v.z + v.w*v.w;
    #pragma unroll
    for (int off = 16; off > 0; off >>= 1) {
        s  += __shfl_xor_sync(0xffffffffu, s,  off);
        ss += __shfl_xor_sync(0xffffffffu, ss, off);
    }
    __shared__ float sbuf[8], ssbuf[8], red[2];
    int warp = tid >> 5, lane = tid & 31;
    if (lane == 0) { sbuf[warp] = s; ssbuf[warp] = ss; }
    __syncthreads();
    if (tid < 32) {
        float a = (tid < 8) ? sbuf[tid]  : 0.f;
        float c = (tid < 8) ? ssbuf[tid] : 0.f;
        #pragma unroll
        for (int off = 4; off > 0; off >>= 1) {
            a += __shfl_xor_sync(0xffffffffu, a, off);
            c += __shfl_xor_sync(0xffffffffu, c, off);
        }
        if (tid == 0) { red[0] = a; red[1] = c; }
    }
    __syncthreads();
    float mu   = red[0] * (1.0f / EMB);
    float var  = red[1] * (1.0f / EMB) - mu * mu;
    float rstd = rsqrtf(var + 1e-5f);
    float4 gg = ((const float4*)g)[tid];
    float4 bb = ((const float4*)b)[tid];
    __half2 p0 = __floats2half2_rn((v.x - mu) * rstd * gg.x + bb.x,
                                   (v.y - mu) * rstd * gg.y + bb.y);
    __half2 p1 = __floats2half2_rn((v.z - mu) * rstd * gg.z + bb.z,
                                   (v.w - mu) * rstd * gg.w + bb.w);
    uint2 pk;
    pk.x = *(unsigned*)&p0; pk.y = *(unsigned*)&p1;
    ((uint2*)(out + (size_t)row * EMB))[tid] = pk;
}

// ---------------- FP16 tensor-core GEMM, BK=64, 3-stage cp.async ------------
// C[M,N] = A[M,K] @ Wt[N,K]^T. 128x128 tile, 256 threads, 8 warps 4(M)x2(N).
// Pitch 72 halves (144B = 36 words: +4 banks/row, fragment reads conflict-free).
#define APH 72
#define HALF_STG (128 * APH)                 // halves per matrix per stage
#define STG_BYTES (2 * HALF_STG * 2)         // A + B, bytes (36864)
#define NSTAGE 3
#define GEMM_SMEM (NSTAGE * STG_BYTES)

#define GEMM_ISSUE(k0, buf) do {                                                \
    _Pragma("unroll")                                                           \
    for (int l = 0; l < 4; l++) {                                               \
        int idx = tid + l * 256;                                                \
        int r = idx >> 3, c = idx & 7;                                          \
        const __half* src = A + (size_t)(m0 + r) * K + (k0) + c * 8;            \
        CP_ASYNC16(as_base + (unsigned)((buf) * STG_BYTES + r * 144 + c * 16), src); \
    }                                                                           \
    _Pragma("unroll")                                                           \
    for (int l = 0; l < 4; l++) {                                               \
        int idx = tid + l * 256;                                                \
        int r = idx >> 3, c = idx & 7;                                          \
        const __half* src = Wt + (size_t)(n0 + r) * K + (k0) + c * 8;           \
        CP_ASYNC16(bs_base + (unsigned)((buf) * STG_BYTES + r * 144 + c * 16), src); \
    }                                                                           \
    CP_COMMIT();                                                                \
} while (0)

template<bool BIAS, bool GELU, bool RES, bool OUTH>
__global__ void __launch_bounds__(256, 2) gemm_f16_kernel(
    const __half* __restrict__ A, const __half* __restrict__ Wt,
    const float* __restrict__ bias, const float* __restrict__ res,
    void* __restrict__ Cv, int M, int N, int K)
{
    extern __shared__ __half smh[];
    __half* As = smh;                                // per stage: [128][APH]
    __half* Bs = smh + HALF_STG;

    const int tid  = threadIdx.x;
    const int lane = tid & 31;
    const int warp = tid >> 5;
    const int wm   = warp & 3;
    const int wn   = warp >> 2;
    const int g    = lane >> 2;
    const int t4   = lane & 3;
    const int m0 = blockIdx.y * 128, n0 = blockIdx.x * 128;

    unsigned as_base = (unsigned)__cvta_generic_to_shared(As);
    unsigned bs_base = (unsigned)__cvta_generic_to_shared(Bs);

    float acc[2][8][4];
    #pragma unroll
    for (int i = 0; i < 2; i++)
        #pragma unroll
        for (int j = 0; j < 8; j++)
            #pragma unroll
            for (int q = 0; q < 4; q++) acc[i][j][q] = 0.f;

    const int T = K / 64;
    GEMM_ISSUE(0, 0);
    GEMM_ISSUE(64, 1);

    int rd = 0, wr = 2;
    for (int it = 0; it < T; it++) {
        if (it + 1 < T) CP_WAIT1(); else CP_WAIT0();
        __syncthreads();
        if (it + 2 < T) {
            GEMM_ISSUE((it + 2) * 64, wr);
            wr = (wr == 2) ? 0 : wr + 1;
        }

        const __half* Asb = As + rd * (STG_BYTES / 2);
        const __half* Bsb = Bs + rd * (STG_BYTES / 2);
        rd = (rd == 2) ? 0 : rd + 1;

        #pragma unroll
        for (int ks = 0; ks < 4; ks++) {
            const int kb = ks * 16;
            unsigned b[8][2], a[2][4];
            #pragma unroll
            for (int jn = 0; jn < 8; jn++) {
                int n = wn * 64 + jn * 8 + g;
                b[jn][0] = *(const unsigned*)&Bsb[n * APH + kb + 2 * t4];
                b[jn][1] = *(const unsigned*)&Bsb[n * APH + kb + 8 + 2 * t4];
            }
            #pragma unroll
            for (int im = 0; im < 2; im++) {
                int row = wm * 32 + im * 16 + g;
                a[im][0] = *(const unsigned*)&Asb[row       * APH + kb + 2 * t4];
                a[im][1] = *(const unsigned*)&Asb[(row + 8) * APH + kb + 2 * t4];
                a[im][2] = *(const unsigned*)&Asb[row       * APH + kb + 8 + 2 * t4];
                a[im][3] = *(const unsigned*)&Asb[(row + 8) * APH + kb + 8 + 2 * t4];
            }
            #pragma unroll
            for (int im = 0; im < 2; im++)
                #pragma unroll
                for (int jn = 0; jn < 8; jn++)
                    MMA_F16(acc[im][jn][0], acc[im][jn][1], acc[im][jn][2], acc[im][jn][3],
                            a[im][0], a[im][1], a[im][2], a[im][3],
                            b[jn][0], b[jn][1]);
        }
        __syncthreads();
    }

    // ---- epilogue ----
    #pragma unroll
    for (int im = 0; im < 2; im++) {
        int r0 = m0 + wm * 32 + im * 16 + g;     // rows r0 and r0+8
        #pragma unroll
        for (int jn = 0; jn < 8; jn++) {
            int c = n0 + wn * 64 + jn * 8 + t4 * 2;
            float v[4] = { acc[im][jn][0], acc[im][jn][1],
                           acc[im][jn][2], acc[im][jn][3] };
            if (BIAS) {
                float2 bq = *(const float2*)(bias + c);
                v[0] += bq.x; v[1] += bq.y; v[2] += bq.x; v[3] += bq.y;
            }
            if (GELU) {
                #pragma unroll
                for (int q = 0; q < 4; q++)
                    v[q] = 0.5f * v[q] * (1.0f + erff(v[q] * 0.70710678118654752f));
            }
            if (RES) {
                float2 rlo = *(const float2*)(res + (size_t)r0 * N + c);
                float2 rhi = *(const float2*)(res + (size_t)(r0 + 8) * N + c);
                v[0] += rlo.x; v[1] += rlo.y; v[2] += rhi.x; v[3] += rhi.y;
            }
            if (OUTH) {
                __half* C = (__half*)Cv;
                *(__half2*)(C + (size_t)r0 * N + c)       = __floats2half2_rn(v[0], v[1]);
                *(__half2*)(C + (size_t)(r0 + 8) * N + c) = __floats2half2_rn(v[2], v[3]);
            } else {
                float* C = (float*)Cv;
                float2 lo; lo.x = v[0]; lo.y = v[1];
                float2 hi; hi.x = v[2]; hi.y = v[3];
                *(float2*)(C + (size_t)r0 * N + c)       = lo;
                *(float2*)(C + (size_t)(r0 + 8) * N + c) = hi;
            }
        }
    }
}

// ---------------- Flash attention, fp16 mma, BQ=128, 256 threads ------------
// 8 warps x 16 q-rows; KV tiles of 64. fp32 softmax. Pitch 72 halves.
// K double-buffered via cp.async; V register-prefetched + transposed to Vt[d][kv].
#define FP 72
#define FLASH_SMEM ((128 + 2 * 64 + 64 + 128) * FP * 2)

#define FLASH_K_ISSUE(kvbase, buf) do {                                         \
    _Pragma("unroll")                                                           \
    for (int l = 0; l < 2; l++) {                                               \
        int idx = tid + l * 256;                                                \
        int r = idx >> 3, c = idx & 7;                                          \
        const __half* src = QKV + base_k + (size_t)((kvbase) + r) * QKVN + c * 8; \
        CP_ASYNC16(ks_base + (unsigned)((buf) * 64 * 144 + r * 144 + c * 16), src); \
    }                                                                           \
    CP_COMMIT();                                                                \
} while (0)

__global__ void __launch_bounds__(256) flash_f16_kernel(
    const __half* __restrict__ QKV, __half* __restrict__ O)
{
    extern __shared__ __half smf[];
    __half* Qs  = smf;                    // [128][FP]
    __half* Ks  = Qs  + 128 * FP;         // [2][64][FP]
    __half* Vts = Ks  + 2 * 64 * FP;      // [64][FP]   V^T: [d][kv]
    __half* Ps  = Vts + 64 * FP;          // [128][FP]

    const int tid  = threadIdx.x;
    const int lane = tid & 31;
    const int warp = tid >> 5;            // 0..7
    const int g    = lane >> 2;
    const int t4   = lane & 3;

    const int bh = blockIdx.y;
    const int b = bh >> 4, h = bh & 15;
    const int qb = (int)gridDim.x - 1 - (int)blockIdx.x;   // heavy blocks first
    const int qbase = qb * 128;
    const size_t base_q = ((size_t)b * 2048) * QKVN + h * 64;
    const size_t base_k = base_q + EMB;
    const size_t base_v = base_q + 2 * EMB;
    const size_t base_o = ((size_t)b * 2048) * EMB + h * 64;

    unsigned qs_base = (unsigned)__cvta_generic_to_shared(Qs);
    unsigned ks_base = (unsigned)__cvta_generic_to_shared(Ks);

    // prologue: Q (128 rows) + K tile 0, one cp.async group
    #pragma unroll
    for (int l = 0; l < 4; l++) {
        int idx = tid + l * 256;
        int r = idx >> 3, c = idx & 7;
        const __half* src = QKV + base_q + (size_t)(qbase + r) * QKVN + c * 8;
        CP_ASYNC16(qs_base + (unsigned)(r * 144 + c * 16), src);
    }
    {
        #pragma unroll
        for (int l = 0; l < 2; l++) {
            int idx = tid + l * 256;
            int r = idx >> 3, c = idx & 7;
            const __half* src = QKV + base_k + (size_t)r * QKVN + c * 8;
            CP_ASYNC16(ks_base + (unsigned)(r * 144 + c * 16), src);
        }
        CP_COMMIT();
    }

    // V tile 0: thread owns kv row tid>>2, d-range (tid&3)*16 .. +15
    const int vrow = tid >> 2;
    const int vd0  = (tid & 3) * 16;
    __half2 vreg[8];
    #pragma unroll
    for (int j = 0; j < 8; j++)
        vreg[j] = *(const __half2*)(QKV + base_v + (size_t)vrow * QKVN + vd0 + 2 * j);
    #pragma unroll
    for (int j = 0; j < 8; j++) {
        Vts[(vd0 + 2 * j    ) * FP + vrow] = __low2half(vreg[j]);
        Vts[(vd0 + 2 * j + 1) * FP + vrow] = __high2half(vreg[j]);
    }

    float m0 = -1e30f, m1 = -1e30f, l0 = 0.f, l1 = 0.f;
    float acc[8][4];
    #pragma unroll
    for (int n = 0; n < 8; n++)
        #pragma unroll
        for (int q = 0; q < 4; q++) acc[n][q] = 0.f;

    const int row0l = warp * 16 + g;           // 0..127
    const int grow0 = qbase + row0l;
    const int grow1 = grow0 + 8;
    const float scale = 0.03125f;              // 1/sqrt(1024)
    const int tmax = 2 * qb + 1;

    for (int t = 0; t <= tmax; t++) {
        const int kvbase = t * 64;
        if (t < tmax) {
            FLASH_K_ISSUE(kvbase + 64, (t + 1) & 1);
            #pragma unroll
            for (int j = 0; j < 8; j++)
                vreg[j] = *(const __half2*)(QKV + base_v +
                    (size_t)(kvbase + 64 + vrow) * QKVN + vd0 + 2 * j);
            CP_WAIT1();
        } else {
            CP_WAIT0();
        }
        __syncthreads();   // K[t] + Vt(t) + (t=0) Qs visible

        const __half* Ksb = Ks + (t & 1) * 64 * FP;

        // ---- S = Q @ K^T ----
        float s[8][4];
        #pragma unroll
        for (int n = 0; n < 8; n++)
            #pragma unroll
            for (int q = 0; q < 4; q++) s[n][q] = 0.f;

        #pragma unroll
        for (int ks = 0; ks < 4; ks++) {
            const int kb = ks * 16;
            unsigned a0 = *(const unsigned*)&Qs[(row0l    ) * FP + kb + 2 * t4];
            unsigned a1 = *(const unsigned*)&Qs[(row0l + 8) * FP + kb + 2 * t4];
            unsigned a2 = *(const unsigned*)&Qs[(row0l    ) * FP + kb + 8 + 2 * t4];
            unsigned a3 = *(const unsigned*)&Qs[(row0l + 8) * FP + kb + 8 + 2 * t4];
            #pragma unroll
            for (int n = 0; n < 8; n++) {
                int kr = n * 8 + g;
                unsigned b0 = *(const unsigned*)&Ksb[kr * FP + kb + 2 * t4];
                unsigned b1 = *(const unsigned*)&Ksb[kr * FP + kb + 8 + 2 * t4];
                MMA_F16(s[n][0], s[n][1], s[n][2], s[n][3], a0, a1, a2, a3, b0, b1);
            }
        }

        // ---- scale + causal mask (only last two tiles can clip) ----
        const bool diag = (kvbase + 63 > qbase);
        #pragma unroll
        for (int n = 0; n < 8; n++) {
            int c0 = kvbase + n * 8 + 2 * t4;
            s[n][0] *= scale; s[n][1] *= scale;
            s[n][2] *= scale; s[n][3] *= scale;
            if (diag) {
                if (c0     > grow0) s[n][0] = -1e30f;
                if (c0 + 1 > grow0) s[n][1] = -1e30f;
                if (c0     > grow1) s[n][2] = -1e30f;
                if (c0 + 1 > grow1) s[n][3] = -1e30f;
            }
        }

        // ---- online softmax (fp32) ----
        float mx0 = -1e30f, mx1 = -1e30f;
        #pragma unroll
        for (int n = 0; n < 8; n++) {
            mx0 = fmaxf(mx0, fmaxf(s[n][0], s[n][1]));
            mx1 = fmaxf(mx1, fmaxf(s[n][2], s[n][3]));
        }
        mx0 = fmaxf(mx0, __shfl_xor_sync(0xffffffffu, mx0, 1));
        mx0 = fmaxf(mx0, __shfl_xor_sync(0xffffffffu, mx0, 2));
        mx1 = fmaxf(mx1, __shfl_xor_sync(0xffffffffu, mx1, 1));
        mx1 = fmaxf(mx1, __shfl_xor_sync(0xffffffffu, mx1, 2));

        float mn0 = fmaxf(m0, mx0), mn1 = fmaxf(m1, mx1);
        float al0 = __expf(m0 - mn0), al1 = __expf(m1 - mn1);
        m0 = mn0; m1 = mn1;

        float rs0 = 0.f, rs1 = 0.f;
        #pragma unroll
        for (int n = 0; n < 8; n++) {
            s[n][0] = __expf(s[n][0] - mn0);
            s[n][1] = __expf(s[n][1] - mn0);
            s[n][2] = __expf(s[n][2] - mn1);
            s[n][3] = __expf(s[n][3] - mn1);
            rs0 += s[n][0] + s[n][1];
            rs1 += s[n][2] + s[n][3];
        }
        rs0 += __shfl_xor_sync(0xffffffffu, rs0, 1);
        rs0 += __shfl_xor_sync(0xffffffffu, rs0, 2);
        rs1 += __shfl_xor_sync(0xffffffffu, rs1, 1);
        rs1 += __shfl_xor_sync(0xffffffffu, rs1, 2);
        l0 = l0 * al0 + rs0;
        l1 = l1 * al1 + rs1;

        #pragma unroll
        for (int n = 0; n < 8; n++) {
            acc[n][0] *= al0; acc[n][1] *= al0;
            acc[n][2] *= al1; acc[n][3] *= al1;
            *(__half2*)&Ps[(row0l    ) * FP + n * 8 + 2 * t4] =
                __floats2half2_rn(s[n][0], s[n][1]);
            *(__half2*)&Ps[(row0l + 8) * FP + n * 8 + 2 * t4] =
                __floats2half2_rn(s[n][2], s[n][3]);
        }
        __syncwarp();   // each warp reads only its own P rows

        // ---- acc += P @ V  (B = Vt[d][kv]) ----
        #pragma unroll
        for (int ks = 0; ks < 4; ks++) {
            const int kb = ks * 16;
            unsigned a0 = *(const unsigned*)&Ps[(row0l    ) * FP + kb + 2 * t4];
            unsigned a1 = *(const unsigned*)&Ps[(row0l + 8) * FP + kb + 2 * t4];
            unsigned a2 = *(const unsigned*)&Ps[(row0l    ) * FP + kb + 8 + 2 * t4];
            unsigned a3 = *(const unsigned*)&Ps[(row0l + 8) * FP + kb + 8 + 2 * t4];
            #pragma unroll
            for (int n = 0; n < 8; n++) {
                int d = n * 8 + g;
                unsigned b0 = *(const unsigned*)&Vts[d * FP + kb + 2 * t4];
                unsigned b1 = *(const unsigned*)&Vts[d * FP + kb + 8 + 2 * t4];
                MMA_F16(acc[n][0], acc[n][1], acc[n][2], acc[n][3], a0, a1, a2, a3, b0, b1);
            }
        }
        __syncthreads();   // all warps done reading Vts

        if (t < tmax) {
            #pragma unroll
            for (int j = 0; j < 8; j++) {
                Vts[(vd0 + 2 * j    ) * FP + vrow] = __low2half(vreg[j]);
                Vts[(vd0 + 2 * j + 1) * FP + vrow] = __high2half(vreg[j]);
            }
        }
    }

    // ---- write O = acc / l as fp16 ----
    float inv0 = 1.0f / l0, inv1 = 1.0f / l1;
    #pragma unroll
    for (int n = 0; n < 8; n++) {
        int c = n * 8 + 2 * t4;
        *(__half2*)(O + base_o + (size_t)grow0 * EMB + c) =
            __floats2half2_rn(acc[n][0] * inv0, acc[n][1] * inv0);
        *(__half2*)(O + base_o + (size_t)grow1 * EMB + c) =
            __floats2half2_rn(acc[n][2] * inv1, acc[n][3] * inv1);
    }
}

// ---------------- launch ----------------------------------------------------
extern "C" void kernel_launch(void* const* d_in, const int* in_sizes, int n_in,
                              void* d_out, int out_size)
{
    const float* x   = (const float*)d_in[0];
    const float* Wq  = (const float*)d_in[1];
    const float* bq  = (const float*)d_in[2];
    const float* Wk  = (const float*)d_in[3];
    const float* bk  = (const float*)d_in[4];
    const float* Wv  = (const float*)d_in[5];
    const float* bv  = (const float*)d_in[6];
    const float* Wo  = (const float*)d_in[7];
    const float* W1  = (const float*)d_in[8];
    const float* b1  = (const float*)d_in[9];
    const float* W2  = (const float*)d_in[10];
    const float* b2  = (const float*)d_in[11];
    const float* g1  = (const float*)d_in[12];
    const float* be1 = (const float*)d_in[13];
    const float* g2  = (const float*)d_in[14];
    const float* be2 = (const float*)d_in[15];
    float* out = (float*)d_out;

    __half *ln1h, *qkvh, *zh, *ln2h, *ffh, *wqkv, *wo, *w1t, *w2t;
    float *hb, *bqkv;
    cudaGetSymbolAddress((void**)&ln1h, g_ln1h);
    cudaGetSymbolAddress((void**)&qkvh, g_qkvh);
    cudaGetSymbolAddress((void**)&zh,   g_zh);
    cudaGetSymbolAddress((void**)&hb,   g_h);
    cudaGetSymbolAddress((void**)&ln2h, g_ln2h);
    cudaGetSymbolAddress((void**)&ffh,  g_ffh);
    cudaGetSymbolAddress((void**)&wqkv, g_wqkv);
    cudaGetSymbolAddress((void**)&bqkv, g_bqkv);
    cudaGetSymbolAddress((void**)&wo,   g_wo);
    cudaGetSymbolAddress((void**)&w1t,  g_w1t);
    cudaGetSymbolAddress((void**)&w2t,  g_w2t);

    cudaFuncSetAttribute(gemm_f16_kernel<true,  false, false, true >,
                         cudaFuncAttributeMaxDynamicSharedMemorySize, GEMM_SMEM);
    cudaFuncSetAttribute(gemm_f16_kernel<false, false, true,  false>,
                         cudaFuncAttributeMaxDynamicSharedMemorySize, GEMM_SMEM);
    cudaFuncSetAttribute(gemm_f16_kernel<true,  true,  false, true >,
                         cudaFuncAttributeMaxDynamicSharedMemorySize, GEMM_SMEM);
    cudaFuncSetAttribute(gemm_f16_kernel<true,  false, true,  false>,
                         cudaFuncAttributeMaxDynamicSharedMemorySize, GEMM_SMEM);
    cudaFuncSetAttribute(flash_f16_kernel,
                         cudaFuncAttributeMaxDynamicSharedMemorySize, FLASH_SMEM);

    // 0) weight prep (single fused launch + bias pack)
    prep_weights_kernel<<<12288, 256>>>(Wq, Wk, Wv, Wo, W1, W2, wqkv, wo, w1t, w2t);
    pack_qkv_b_kernel<<<(QKVN + 255) / 256, 256>>>(bq, bk, bv, bqkv);

    // 1) ln1 = fp16(LN(x))
    layernorm_kernel<<<NTOK, 256>>>(x, g1, be1, ln1h);

    // 2) fused QKV projection (fp16 mma), fp16 output
    gemm_f16_kernel<true, false, false, true><<<dim3(QKVN / 128, NTOK / 128), 256, GEMM_SMEM>>>(
        ln1h, wqkv, bqkv, nullptr, qkvh, NTOK, QKVN, EMB);

    // 3) causal flash attention (fp16 mma, fp32 softmax), BQ=128
    flash_f16_kernel<<<dim3(16, 32), 256, FLASH_SMEM>>>(qkvh, zh);

    // 4) h = x + z @ Wo  (fp32 output)
    gemm_f16_kernel<false, false, true, false><<<dim3(EMB / 128, NTOK / 128), 256, GEMM_SMEM>>>(
        zh, wo, nullptr, x, hb, NTOK, EMB, EMB);

    // 5) ln2 = fp16(LN(h))
    layernorm_kernel<<<NTOK, 256>>>(hb, g2, be2, ln2h);

    // 6) ff = fp16(gelu(ln2 @ W1 + b1))
    gemm_f16_kernel<true, true, false, true><<<dim3(FFD / 128, NTOK / 128), 256, GEMM_SMEM>>>(
        ln2h, w1t, b1, nullptr, ffh, NTOK, FFD, EMB);

    // 7) out = h + ff @ W2 + b2  (fp32 output)
    gemm_f16_kernel<true, false, true, false><<<dim3(EMB / 128, NTOK / 128), 256, GEMM_SMEM>>>(
        ffh, w2t, b2, hb, out, NTOK, EMB, FFD);
}

// round 15
// speedup vs baseline: 6.6389x; 1.1063x over previous
#include <cuda_runtime.h>
#include <cuda_fp16.h>
#include <math.h>

// ---------------- scratch (device globals; no allocation allowed) ----------
#define NTOK 4096            // B*S = 2*2048
#define EMB  1024
#define FFD  4096
#define QKVN 3072

__device__ __half g_ln1h[NTOK * EMB];
__device__ __half g_qkvh[NTOK * QKVN];
__device__ __half g_zh  [NTOK * EMB];
__device__ float  g_h   [NTOK * EMB];
__device__ __half g_ln2h[NTOK * EMB];
__device__ __half g_ffh [NTOK * FFD];
// fp16 TRANSPOSED weights: [N][K] K-major
__device__ __half g_wqkv[QKVN * EMB];
__device__ float  g_bqkv[QKVN];
__device__ __half g_wo  [EMB * EMB];
__device__ __half g_w1t [FFD * EMB];
__device__ __half g_w2t [EMB * FFD];

// ---------------- helpers ---------------------------------------------------
#define CP_ASYNC16(dst_u32, src_ptr) \
    asm volatile("cp.async.cg.shared.global [%0], [%1], 16;" :: "r"(dst_u32), "l"(src_ptr))
#define CP_COMMIT() asm volatile("cp.async.commit_group;")
#define CP_WAIT1()  asm volatile("cp.async.wait_group 1;")
#define CP_WAIT0()  asm volatile("cp.async.wait_group 0;")

#define MMA_F16(d0,d1,d2,d3, a0,a1,a2,a3, b0,b1) \
    asm volatile( \
        "mma.sync.aligned.m16n8k16.row.col.f32.f16.f16.f32 " \
        "{%0,%1,%2,%3}, {%4,%5,%6,%7}, {%8,%9}, {%0,%1,%2,%3};" \
        : "+f"(d0), "+f"(d1), "+f"(d2), "+f"(d3) \
        : "r"(a0), "r"(a1), "r"(a2), "r"(a3), "r"(b0), "r"(b1))

#define LDSM_X4(r0,r1,r2,r3, addr) \
    asm volatile("ldmatrix.sync.aligned.m8n8.x4.shared.b16 {%0,%1,%2,%3}, [%4];" \
        : "=r"(r0), "=r"(r1), "=r"(r2), "=r"(r3) : "r"(addr))

// Per-lane ldmatrix byte offsets for pitch-72-half (144B) tiles.
// A-tile (16 rows x 16 k): quad&1 -> row+8, quad&2 -> col+8  => r0..r3 = a0..a3
// B-tile (16 rows x 16 k): quad&2 -> row+8, quad&1 -> col+8  => r0,r1 = b[j][0..1], r2,r3 = b[j+1][0..1]
#define LDSM_A_LOFF(lane) (((((lane) >> 3) & 1) * 8 + ((lane) & 7)) * 72 + (((lane) >> 4) & 1) * 8) * 2
#define LDSM_B_LOFF(lane) (((((lane) >> 4) & 1) * 8 + ((lane) & 7)) * 72 + (((lane) >> 3) & 1) * 8) * 2

// ---------------- fused weight prep: all 6 transposes in one launch ---------
__global__ void __launch_bounds__(256) prep_weights_kernel(
    const float* __restrict__ Wq, const float* __restrict__ Wk,
    const float* __restrict__ Wv, const float* __restrict__ Wo,
    const float* __restrict__ W1, const float* __restrict__ W2,
    __half* __restrict__ wqkv, __half* __restrict__ wo,
    __half* __restrict__ w1t, __half* __restrict__ w2t)
{
    int bid = blockIdx.x;
    const float* src; __half* dst; int K, N, ti;
    if (bid < 1024)      { src = Wq; dst = wqkv;               K = EMB; N = EMB; ti = bid; }
    else if (bid < 2048) { src = Wk; dst = wqkv + EMB * EMB;   K = EMB; N = EMB; ti = bid - 1024; }
    else if (bid < 3072) { src = Wv; dst = wqkv + 2*EMB*EMB;   K = EMB; N = EMB; ti = bid - 2048; }
    else if (bid < 4096) { src = Wo; dst = wo;                 K = EMB; N = EMB; ti = bid - 3072; }
    else if (bid < 8192) { src = W1; dst = w1t;                K = EMB; N = FFD; ti = bid - 4096; }
    else                 { src = W2; dst = w2t;                K = FFD; N = EMB; ti = bid - 8192; }
    int nx = N / 32;
    int n0 = (ti % nx) * 32, k0 = (ti / nx) * 32;

    __shared__ float tile[32][33];
    int tx = threadIdx.x & 31, ty = threadIdx.x >> 5;
    #pragma unroll
    for (int i = 0; i < 32; i += 8)
        tile[ty + i][tx] = src[(size_t)(k0 + ty + i) * N + n0 + tx];
    __syncthreads();
    #pragma unroll
    for (int i = 0; i < 32; i += 8)
        dst[(size_t)(n0 + ty + i) * K + k0 + tx] = __float2half_rn(tile[tx][ty + i]);
}

__global__ void __launch_bounds__(256) pack_qkv_b_kernel(
    const float* __restrict__ bq, const float* __restrict__ bk,
    const float* __restrict__ bv, float* __restrict__ out)
{
    int i = blockIdx.x * blockDim.x + threadIdx.x;
    if (i >= QKVN) return;
    out[i] = (i < EMB) ? bq[i] : (i < 2 * EMB) ? bk[i - EMB] : bv[i - 2 * EMB];
}

// ---------------- LayerNorm (fp16 output: feeds GEMMs) ----------------------
__global__ void __launch_bounds__(256) layernorm_kernel(
    const float* __restrict__ x, const float* __restrict__ g,
    const float* __restrict__ b, __half* __restrict__ out)
{
    int row = blockIdx.x;
    int tid = threadIdx.x;
    const float4* xr = (const float4*)(x + (size_t)row * EMB);
    float4 v = xr[tid];
    float s  = v.x + v.y + v.z + v.w;
    float ss = v.x*v.x + v.y*v.y + v.z*v.z + v.w*v.w;
    #pragma unroll
    for (int off = 16; off > 0; off >>= 1) {
        s  += __shfl_xor_sync(0xffffffffu, s,  off);
        ss += __shfl_xor_sync(0xffffffffu, ss, off);
    }
    __shared__ float sbuf[8], ssbuf[8], red[2];
    int warp = tid >> 5, lane = tid & 31;
    if (lane == 0) { sbuf[warp] = s; ssbuf[warp] = ss; }
    __syncthreads();
    if (tid < 32) {
        float a = (tid < 8) ? sbuf[tid]  : 0.f;
        float c = (tid < 8) ? ssbuf[tid] : 0.f;
        #pragma unroll
        for (int off = 4; off > 0; off >>= 1) {
            a += __shfl_xor_sync(0xffffffffu, a, off);
            c += __shfl_xor_sync(0xffffffffu, c, off);
        }
        if (tid == 0) { red[0] = a; red[1] = c; }
    }
    __syncthreads();
    float mu   = red[0] * (1.0f / EMB);
    float var  = red[1] * (1.0f / EMB) - mu * mu;
    float rstd = rsqrtf(var + 1e-5f);
    float4 gg = ((const float4*)g)[tid];
    float4 bb = ((const float4*)b)[tid];
    __half2 p0 = __floats2half2_rn((v.x - mu) * rstd * gg.x + bb.x,
                                   (v.y - mu) * rstd * gg.y + bb.y);
    __half2 p1 = __floats2half2_rn((v.z - mu) * rstd * gg.z + bb.z,
                                   (v.w - mu) * rstd * gg.w + bb.w);
    uint2 pk;
    pk.x = *(unsigned*)&p0; pk.y = *(unsigned*)&p1;
    ((uint2*)(out + (size_t)row * EMB))[tid] = pk;
}

// ---------------- FP16 tensor-core GEMM, BK=64, 3-stage cp.async, LDSM ------
#define APH 72
#define HALF_STG (128 * APH)
#define STG_BYTES (2 * HALF_STG * 2)
#define NSTAGE 3
#define GEMM_SMEM (NSTAGE * STG_BYTES)

#define GEMM_ISSUE(k0, buf) do {                                                \
    _Pragma("unroll")                                                           \
    for (int l = 0; l < 4; l++) {                                               \
        int idx = tid + l * 256;                                                \
        int r = idx >> 3, c = idx & 7;                                          \
        const __half* src = A + (size_t)(m0 + r) * K + (k0) + c * 8;            \
        CP_ASYNC16(as_base + (unsigned)((buf) * STG_BYTES + r * 144 + c * 16), src); \
    }                                                                           \
    _Pragma("unroll")                                                           \
    for (int l = 0; l < 4; l++) {                                               \
        int idx = tid + l * 256;                                                \
        int r = idx >> 3, c = idx & 7;                                          \
        const __half* src = Wt + (size_t)(n0 + r) * K + (k0) + c * 8;           \
        CP_ASYNC16(bs_base + (unsigned)((buf) * STG_BYTES + r * 144 + c * 16), src); \
    }                                                                           \
    CP_COMMIT();                                                                \
} while (0)

template<bool BIAS, bool GELU, bool RES, bool OUTH>
__global__ void __launch_bounds__(256, 2) gemm_f16_kernel(
    const __half* __restrict__ A, const __half* __restrict__ Wt,
    const float* __restrict__ bias, const float* __restrict__ res,
    void* __restrict__ Cv, int M, int N, int K)
{
    extern __shared__ __half smh[];
    __half* As = smh;
    __half* Bs = smh + HALF_STG;

    const int tid  = threadIdx.x;
    const int lane = tid & 31;
    const int warp = tid >> 5;
    const int wm   = warp & 3;
    const int wn   = warp >> 2;
    const int g    = lane >> 2;
    const int t4   = lane & 3;
    const int m0 = blockIdx.y * 128, n0 = blockIdx.x * 128;

    unsigned as_base = (unsigned)__cvta_generic_to_shared(As);
    unsigned bs_base = (unsigned)__cvta_generic_to_shared(Bs);
    const unsigned a_loff = LDSM_A_LOFF(lane);
    const unsigned b_loff = LDSM_B_LOFF(lane);

    float acc[2][8][4];
    #pragma unroll
    for (int i = 0; i < 2; i++)
        #pragma unroll
        for (int j = 0; j < 8; j++)
            #pragma unroll
            for (int q = 0; q < 4; q++) acc[i][j][q] = 0.f;

    const int T = K / 64;
    GEMM_ISSUE(0, 0);
    GEMM_ISSUE(64, 1);

    int rd = 0, wr = 2;
    for (int it = 0; it < T; it++) {
        if (it + 1 < T) CP_WAIT1(); else CP_WAIT0();
        __syncthreads();
        if (it + 2 < T) {
            GEMM_ISSUE((it + 2) * 64, wr);
            wr = (wr == 2) ? 0 : wr + 1;
        }

        const unsigned asb = as_base + rd * STG_BYTES;
        const unsigned bsb = bs_base + rd * STG_BYTES;
        rd = (rd == 2) ? 0 : rd + 1;

        #pragma unroll
        for (int ks = 0; ks < 4; ks++) {
            const int kb = ks * 16;
            unsigned a[2][4], b[8][2];
            LDSM_X4(a[0][0], a[0][1], a[0][2], a[0][3],
                    asb + (unsigned)(((wm * 32     ) * APH + kb) * 2) + a_loff);
            LDSM_X4(a[1][0], a[1][1], a[1][2], a[1][3],
                    asb + (unsigned)(((wm * 32 + 16) * APH + kb) * 2) + a_loff);
            #pragma unroll
            for (int j2 = 0; j2 < 4; j2++)
                LDSM_X4(b[2*j2][0], b[2*j2][1], b[2*j2+1][0], b[2*j2+1][1],
                        bsb + (unsigned)(((wn * 64 + j2 * 16) * APH + kb) * 2) + b_loff);
            #pragma unroll
            for (int im = 0; im < 2; im++)
                #pragma unroll
                for (int jn = 0; jn < 8; jn++)
                    MMA_F16(acc[im][jn][0], acc[im][jn][1], acc[im][jn][2], acc[im][jn][3],
                            a[im][0], a[im][1], a[im][2], a[im][3],
                            b[jn][0], b[jn][1]);
        }
        __syncthreads();
    }

    // ---- epilogue ----
    #pragma unroll
    for (int im = 0; im < 2; im++) {
        int r0 = m0 + wm * 32 + im * 16 + g;
        #pragma unroll
        for (int jn = 0; jn < 8; jn++) {
            int c = n0 + wn * 64 + jn * 8 + t4 * 2;
            float v[4] = { acc[im][jn][0], acc[im][jn][1],
                           acc[im][jn][2], acc[im][jn][3] };
            if (BIAS) {
                float2 bq = *(const float2*)(bias + c);
                v[0] += bq.x; v[1] += bq.y; v[2] += bq.x; v[3] += bq.y;
            }
            if (GELU) {
                #pragma unroll
                for (int q = 0; q < 4; q++)
                    v[q] = 0.5f * v[q] * (1.0f + erff(v[q] * 0.70710678118654752f));
            }
            if (RES) {
                float2 rlo = *(const float2*)(res + (size_t)r0 * N + c);
                float2 rhi = *(const float2*)(res + (size_t)(r0 + 8) * N + c);
                v[0] += rlo.x; v[1] += rlo.y; v[2] += rhi.x; v[3] += rhi.y;
            }
            if (OUTH) {
                __half* C = (__half*)Cv;
                *(__half2*)(C + (size_t)r0 * N + c)       = __floats2half2_rn(v[0], v[1]);
                *(__half2*)(C + (size_t)(r0 + 8) * N + c) = __floats2half2_rn(v[2], v[3]);
            } else {
                float* C = (float*)Cv;
                float2 lo; lo.x = v[0]; lo.y = v[1];
                float2 hi; hi.x = v[2]; hi.y = v[3];
                *(float2*)(C + (size_t)r0 * N + c)       = lo;
                *(float2*)(C + (size_t)(r0 + 8) * N + c) = hi;
            }
        }
    }
}

// ---------------- Flash attention, fp16 mma + LDSM, BQ=128, 256 threads -----
#define FP 72
#define FLASH_SMEM ((128 + 2 * 64 + 64 + 128) * FP * 2)

#define FLASH_K_ISSUE(kvbase, buf) do {                                         \
    _Pragma("unroll")                                                           \
    for (int l = 0; l < 2; l++) {                                               \
        int idx = tid + l * 256;                                                \
        int r = idx >> 3, c = idx & 7;                                          \
        const __half* src = QKV + base_k + (size_t)((kvbase) + r) * QKVN + c * 8; \
        CP_ASYNC16(ks_base + (unsigned)((buf) * 64 * 144 + r * 144 + c * 16), src); \
    }                                                                           \
    CP_COMMIT();                                                                \
} while (0)

__global__ void __launch_bounds__(256) flash_f16_kernel(
    const __half* __restrict__ QKV, __half* __restrict__ O)
{
    extern __shared__ __half smf[];
    __half* Qs  = smf;                    // [128][FP]
    __half* Ks  = Qs  + 128 * FP;         // [2][64][FP]
    __half* Vts = Ks  + 2 * 64 * FP;      // [64][FP]   V^T: [d][kv]
    __half* Ps  = Vts + 64 * FP;          // [128][FP]

    const int tid  = threadIdx.x;
    const int lane = tid & 31;
    const int warp = tid >> 5;            // 0..7
    const int g    = lane >> 2;
    const int t4   = lane & 3;

    const int bh = blockIdx.y;
    const int b = bh >> 4, h = bh & 15;
    const int qb = (int)gridDim.x - 1 - (int)blockIdx.x;   // heavy blocks first
    const int qbase = qb * 128;
    const size_t base_q = ((size_t)b * 2048) * QKVN + h * 64;
    const size_t base_k = base_q + EMB;
    const size_t base_v = base_q + 2 * EMB;
    const size_t base_o = ((size_t)b * 2048) * EMB + h * 64;

    unsigned qs_base  = (unsigned)__cvta_generic_to_shared(Qs);
    unsigned ks_base  = (unsigned)__cvta_generic_to_shared(Ks);
    unsigned vts_base = (unsigned)__cvta_generic_to_shared(Vts);
    unsigned ps_base  = (unsigned)__cvta_generic_to_shared(Ps);
    const unsigned a_loff = LDSM_A_LOFF(lane);
    const unsigned b_loff = LDSM_B_LOFF(lane);

    // prologue: Q (128 rows) + K tile 0
    #pragma unroll
    for (int l = 0; l < 4; l++) {
        int idx = tid + l * 256;
        int r = idx >> 3, c = idx & 7;
        const __half* src = QKV + base_q + (size_t)(qbase + r) * QKVN + c * 8;
        CP_ASYNC16(qs_base + (unsigned)(r * 144 + c * 16), src);
    }
    {
        #pragma unroll
        for (int l = 0; l < 2; l++) {
            int idx = tid + l * 256;
            int r = idx >> 3, c = idx & 7;
            const __half* src = QKV + base_k + (size_t)r * QKVN + c * 8;
            CP_ASYNC16(ks_base + (unsigned)(r * 144 + c * 16), src);
        }
        CP_COMMIT();
    }

    // V tile 0: thread owns kv row tid>>2, d-range (tid&3)*16 .. +15
    const int vrow = tid >> 2;
    const int vd0  = (tid & 3) * 16;
    __half2 vreg[8];
    #pragma unroll
    for (int j = 0; j < 8; j++)
        vreg[j] = *(const __half2*)(QKV + base_v + (size_t)vrow * QKVN + vd0 + 2 * j);
    #pragma unroll
    for (int j = 0; j < 8; j++) {
        Vts[(vd0 + 2 * j    ) * FP + vrow] = __low2half(vreg[j]);
        Vts[(vd0 + 2 * j + 1) * FP + vrow] = __high2half(vreg[j]);
    }

    float m0 = -1e30f, m1 = -1e30f, l0 = 0.f, l1 = 0.f;
    float acc[8][4];
    #pragma unroll
    for (int n = 0; n < 8; n++)
        #pragma unroll
        for (int q = 0; q < 4; q++) acc[n][q] = 0.f;

    const int row0l = warp * 16 + g;
    const int grow0 = qbase + row0l;
    const int grow1 = grow0 + 8;
    const float scale = 0.03125f;       // 1/sqrt(1024)
    const int tmax = 2 * qb + 1;

    for (int t = 0; t <= tmax; t++) {
        const int kvbase = t * 64;
        if (t < tmax) {
            FLASH_K_ISSUE(kvbase + 64, (t + 1) & 1);
            #pragma unroll
            for (int j = 0; j < 8; j++)
                vreg[j] = *(const __half2*)(QKV + base_v +
                    (size_t)(kvbase + 64 + vrow) * QKVN + vd0 + 2 * j);
            CP_WAIT1();
        } else {
            CP_WAIT0();
        }
        __syncthreads();

        const unsigned ksb = ks_base + (t & 1) * 64 * 144;

        // ---- S = Q @ K^T ----
        float s[8][4];
        #pragma unroll
        for (int n = 0; n < 8; n++)
            #pragma unroll
            for (int q = 0; q < 4; q++) s[n][q] = 0.f;

        #pragma unroll
        for (int ks = 0; ks < 4; ks++) {
            const int kb = ks * 16;
            unsigned a[4], bfr[8][2];
            LDSM_X4(a[0], a[1], a[2], a[3],
                    qs_base + (unsigned)(((warp * 16) * FP + kb) * 2) + a_loff);
            #pragma unroll
            for (int j2 = 0; j2 < 4; j2++)
                LDSM_X4(bfr[2*j2][0], bfr[2*j2][1], bfr[2*j2+1][0], bfr[2*j2+1][1],
                        ksb + (unsigned)(((j2 * 16) * FP + kb) * 2) + b_loff);
            #pragma unroll
            for (int n = 0; n < 8; n++)
                MMA_F16(s[n][0], s[n][1], s[n][2], s[n][3],
                        a[0], a[1], a[2], a[3], bfr[n][0], bfr[n][1]);
        }

        // ---- scale + causal mask ----
        const bool diag = (kvbase + 63 > qbase);
        #pragma unroll
        for (int n = 0; n < 8; n++) {
            int c0 = kvbase + n * 8 + 2 * t4;
            s[n][0] *= scale; s[n][1] *= scale;
            s[n][2] *= scale; s[n][3] *= scale;
            if (diag) {
                if (c0     > grow0) s[n][0] = -1e30f;
                if (c0 + 1 > grow0) s[n][1] = -1e30f;
                if (c0     > grow1) s[n][2] = -1e30f;
                if (c0 + 1 > grow1) s[n][3] = -1e30f;
            }
        }

        // ---- online softmax (fp32) ----
        float mx0 = -1e30f, mx1 = -1e30f;
        #pragma unroll
        for (int n = 0; n < 8; n++) {
            mx0 = fmaxf(mx0, fmaxf(s[n][0], s[n][1]));
            mx1 = fmaxf(mx1, fmaxf(s[n][2], s[n][3]));
        }
        mx0 = fmaxf(mx0, __shfl_xor_sync(0xffffffffu, mx0, 1));
        mx0 = fmaxf(mx0, __shfl_xor_sync(0xffffffffu, mx0, 2));
        mx1 = fmaxf(mx1, __shfl_xor_sync(0xffffffffu, mx1, 1));
        mx1 = fmaxf(mx1, __shfl_xor_sync(0xffffffffu, mx1, 2));

        float mn0 = fmaxf(m0, mx0), mn1 = fmaxf(m1, mx1);
        float al0 = __expf(m0 - mn0), al1 = __expf(m1 - mn1);
        m0 = mn0; m1 = mn1;

        float rs0 = 0.f, rs1 = 0.f;
        #pragma unroll
        for (int n = 0; n < 8; n++) {
            s[n][0] = __expf(s[n][0] - mn0);
            s[n][1] = __expf(s[n][1] - mn0);
            s[n][2] = __expf(s[n][2] - mn1);
            s[n][3] = __expf(s[n][3] - mn1);
            rs0 += s[n][0] + s[n][1];
            rs1 += s[n][2] + s[n][3];
        }
        rs0 += __shfl_xor_sync(0xffffffffu, rs0, 1);
        rs0 += __shfl_xor_sync(0xffffffffu, rs0, 2);
        rs1 += __shfl_xor_sync(0xffffffffu, rs1, 1);
        rs1 += __shfl_xor_sync(0xffffffffu, rs1, 2);
        l0 = l0 * al0 + rs0;
        l1 = l1 * al1 + rs1;

        #pragma unroll
        for (int n = 0; n < 8; n++) {
            acc[n][0] *= al0; acc[n][1] *= al0;
            acc[n][2] *= al1; acc[n][3] *= al1;
            *(__half2*)&Ps[(row0l    ) * FP + n * 8 + 2 * t4] =
                __floats2half2_rn(s[n][0], s[n][1]);
            *(__half2*)&Ps[(row0l + 8) * FP + n * 8 + 2 * t4] =
                __floats2half2_rn(s[n][2], s[n][3]);
        }
        __syncwarp();   // each warp reads only its own P rows

        // ---- acc += P @ V  (B = Vt[d][kv]) ----
        #pragma unroll
        for (int ks = 0; ks < 4; ks++) {
            const int kb = ks * 16;
            unsigned a[4], bfr[8][2];
            LDSM_X4(a[0], a[1], a[2], a[3],
                    ps_base + (unsigned)(((warp * 16) * FP + kb) * 2) + a_loff);
            #pragma unroll
            for (int j2 = 0; j2 < 4; j2++)
                LDSM_X4(bfr[2*j2][0], bfr[2*j2][1], bfr[2*j2+1][0], bfr[2*j2+1][1],
                        vts_base + (unsigned)(((j2 * 16) * FP + kb) * 2) + b_loff);
            #pragma unroll
            for (int n = 0; n < 8; n++)
                MMA_F16(acc[n][0], acc[n][1], acc[n][2], acc[n][3],
                        a[0], a[1], a[2], a[3], bfr[n][0], bfr[n][1]);
        }
        __syncthreads();   // all warps done reading Vts

        if (t < tmax) {
            #pragma unroll
            for (int j = 0; j < 8; j++) {
                Vts[(vd0 + 2 * j    ) * FP + vrow] = __low2half(vreg[j]);
                Vts[(vd0 + 2 * j + 1) * FP + vrow] = __high2half(vreg[j]);
            }
        }
    }

    // ---- write O = acc / l as fp16 ----
    float inv0 = 1.0f / l0, inv1 = 1.0f / l1;
    #pragma unroll
    for (int n = 0; n < 8; n++) {
        int c = n * 8 + 2 * t4;
        *(__half2*)(O + base_o + (size_t)grow0 * EMB + c) =
            __floats2half2_rn(acc[n][0] * inv0, acc[n][1] * inv0);
        *(__half2*)(O + base_o + (size_t)grow1 * EMB + c) =
            __floats2half2_rn(acc[n][2] * inv1, acc[n][3] * inv1);
    }
}

// ---------------- launch ----------------------------------------------------
extern "C" void kernel_launch(void* const* d_in, const int* in_sizes, int n_in,
                              void* d_out, int out_size)
{
    const float* x   = (const float*)d_in[0];
    const float* Wq  = (const float*)d_in[1];
    const float* bq  = (const float*)d_in[2];
    const float* Wk  = (const float*)d_in[3];
    const float* bk  = (const float*)d_in[4];
    const float* Wv  = (const float*)d_in[5];
    const float* bv  = (const float*)d_in[6];
    const float* Wo  = (const float*)d_in[7];
    const float* W1  = (const float*)d_in[8];
    const float* b1  = (const float*)d_in[9];
    const float* W2  = (const float*)d_in[10];
    const float* b2  = (const float*)d_in[11];
    const float* g1  = (const float*)d_in[12];
    const float* be1 = (const float*)d_in[13];
    const float* g2  = (const float*)d_in[14];
    const float* be2 = (const float*)d_in[15];
    float* out = (float*)d_out;

    __half *ln1h, *qkvh, *zh, *ln2h, *ffh, *wqkv, *wo, *w1t, *w2t;
    float *hb, *bqkv;
    cudaGetSymbolAddress((void**)&ln1h, g_ln1h);
    cudaGetSymbolAddress((void**)&qkvh, g_qkvh);
    cudaGetSymbolAddress((void**)&zh,   g_zh);
    cudaGetSymbolAddress((void**)&hb,   g_h);
    cudaGetSymbolAddress((void**)&ln2h, g_ln2h);
    cudaGetSymbolAddress((void**)&ffh,  g_ffh);
    cudaGetSymbolAddress((void**)&wqkv, g_wqkv);
    cudaGetSymbolAddress((void**)&bqkv, g_bqkv);
    cudaGetSymbolAddress((void**)&wo,   g_wo);
    cudaGetSymbolAddress((void**)&w1t,  g_w1t);
    cudaGetSymbolAddress((void**)&w2t,  g_w2t);

    cudaFuncSetAttribute(gemm_f16_kernel<true,  false, false, true >,
                         cudaFuncAttributeMaxDynamicSharedMemorySize, GEMM_SMEM);
    cudaFuncSetAttribute(gemm_f16_kernel<false, false, true,  false>,
                         cudaFuncAttributeMaxDynamicSharedMemorySize, GEMM_SMEM);
    cudaFuncSetAttribute(gemm_f16_kernel<true,  true,  false, true >,
                         cudaFuncAttributeMaxDynamicSharedMemorySize, GEMM_SMEM);
    cudaFuncSetAttribute(gemm_f16_kernel<true,  false, true,  false>,
                         cudaFuncAttributeMaxDynamicSharedMemorySize, GEMM_SMEM);
    cudaFuncSetAttribute(flash_f16_kernel,
                         cudaFuncAttributeMaxDynamicSharedMemorySize, FLASH_SMEM);

    // 0) weight prep (single fused launch + bias pack)
    prep_weights_kernel<<<12288, 256>>>(Wq, Wk, Wv, Wo, W1, W2, wqkv, wo, w1t, w2t);
    pack_qkv_b_kernel<<<(QKVN + 255) / 256, 256>>>(bq, bk, bv, bqkv);

    // 1) ln1 = fp16(LN(x))
    layernorm_kernel<<<NTOK, 256>>>(x, g1, be1, ln1h);

    // 2) fused QKV projection (fp16 mma), fp16 output
    gemm_f16_kernel<true, false, false, true><<<dim3(QKVN / 128, NTOK / 128), 256, GEMM_SMEM>>>(
        ln1h, wqkv, bqkv, nullptr, qkvh, NTOK, QKVN, EMB);

    // 3) causal flash attention (fp16 mma, fp32 softmax), BQ=128
    flash_f16_kernel<<<dim3(16, 32), 256, FLASH_SMEM>>>(qkvh, zh);

    // 4) h = x + z @ Wo  (fp32 output)
    gemm_f16_kernel<false, false, true, false><<<dim3(EMB / 128, NTOK / 128), 256, GEMM_SMEM>>>(
        zh, wo, nullptr, x, hb, NTOK, EMB, EMB);

    // 5) ln2 = fp16(LN(h))
    layernorm_kernel<<<NTOK, 256>>>(hb, g2, be2, ln2h);

    // 6) ff = fp16(gelu(ln2 @ W1 + b1))
    gemm_f16_kernel<true, true, false, true><<<dim3(FFD / 128, NTOK / 128), 256, GEMM_SMEM>>>(
        ln2h, w1t, b1, nullptr, ffh, NTOK, FFD, EMB);

    // 7) out = h + ff @ W2 + b2  (fp32 output)
    gemm_f16_kernel<true, false, true, false><<<dim3(EMB / 128, NTOK / 128), 256, GEMM_SMEM>>>(
        ffh, w2t, b2, hb, out, NTOK, EMB, FFD);
}